// round 1
// baseline (speedup 1.0000x reference)
#include <cuda_runtime.h>
#include <cuda_bf16.h>
#include <math.h>

#define Bsz 2
#define Tseq 4096
#define Cdim 768
#define Hn 12
#define HD 64
#define C3 (3*Cdim)

// ---------------- scratch (no allocs allowed) ----------------
__device__ __align__(16) float g_qkv[(size_t)Bsz * Tseq * C3];   // [B,T,3C]
__device__ __align__(16) float g_y  [(size_t)Bsz * Tseq * Cdim]; // [B,T,C]

// ---------------- generic tiled fp32 GEMM: C = A[MxK] @ B[KxN] + bias ----------------
#define GBM 64
#define GBN 64
#define GBK 16
#define GTM 4
#define GTN 4

__global__ __launch_bounds__(256)
void gemm_bias_kernel(const float* __restrict__ A, const float* __restrict__ B,
                      const float* __restrict__ bias, float* __restrict__ C,
                      int M, int N, int K)
{
    __shared__ float As[GBK][GBM];   // A tile, transposed
    __shared__ float Bs[GBK][GBN];

    const int tid = threadIdx.x;
    const int tx  = tid & 15;        // 0..15 col group
    const int ty  = tid >> 4;        // 0..15 row group
    const int rowBase = blockIdx.y * GBM;
    const int colBase = blockIdx.x * GBN;

    // load indices
    const int a_row  = tid >> 2;     // 0..63
    const int a_col4 = tid & 3;      // 0..3 (float4 within the 16-wide k slab)
    const int b_row  = tid >> 4;     // 0..15
    const int b_col4 = tid & 15;     // 0..15

    float acc[GTM][GTN];
    #pragma unroll
    for (int i = 0; i < GTM; i++)
        #pragma unroll
        for (int j = 0; j < GTN; j++) acc[i][j] = 0.f;

    for (int k0 = 0; k0 < K; k0 += GBK) {
        float4 av = *(const float4*)&A[(size_t)(rowBase + a_row) * K + k0 + a_col4 * 4];
        As[a_col4*4 + 0][a_row] = av.x;
        As[a_col4*4 + 1][a_row] = av.y;
        As[a_col4*4 + 2][a_row] = av.z;
        As[a_col4*4 + 3][a_row] = av.w;
        *(float4*)&Bs[b_row][b_col4 * 4] =
            *(const float4*)&B[(size_t)(k0 + b_row) * N + colBase + b_col4 * 4];
        __syncthreads();

        #pragma unroll
        for (int kk = 0; kk < GBK; kk++) {
            float4 ra = *(const float4*)&As[kk][ty * GTM];
            float4 rb = *(const float4*)&Bs[kk][tx * GTN];
            float rav[4] = {ra.x, ra.y, ra.z, ra.w};
            float rbv[4] = {rb.x, rb.y, rb.z, rb.w};
            #pragma unroll
            for (int i = 0; i < GTM; i++)
                #pragma unroll
                for (int j = 0; j < GTN; j++)
                    acc[i][j] = fmaf(rav[i], rbv[j], acc[i][j]);
        }
        __syncthreads();
    }

    #pragma unroll
    for (int i = 0; i < GTM; i++) {
        const int r = rowBase + ty * GTM + i;
        const int c = colBase + tx * GTN;
        float4 bv = *(const float4*)&bias[c];
        float4 ov;
        ov.x = acc[i][0] + bv.x;
        ov.y = acc[i][1] + bv.y;
        ov.z = acc[i][2] + bv.z;
        ov.w = acc[i][3] + bv.w;
        *(float4*)&C[(size_t)r * N + c] = ov;
    }
}

// ---------------- causal flash attention, fp32, 1 thread = 1 query row ----------------
#define AT_BM 128
#define AT_BN 32

__global__ __launch_bounds__(128)
void attn_kernel(const float* __restrict__ qkv, float* __restrict__ y)
{
    const int bh = blockIdx.y;
    const int b  = bh / Hn;
    const int h  = bh % Hn;
    const int q0 = blockIdx.x * AT_BM;
    const int tid = threadIdx.x;           // 0..127 (query row within tile)
    const int qi  = q0 + tid;
    const float scale = 0.125f;            // 1/sqrt(64)

    __shared__ float Ks[AT_BN][HD];
    __shared__ float Vs[AT_BN][HD];
    __shared__ float Ss[AT_BN][AT_BM];     // scores: [key][query-thread], conflict-free

    // load q row into registers
    float q[HD];
    {
        const float* qrow = qkv + ((size_t)(b * Tseq + qi) * C3) + h * HD;
        #pragma unroll
        for (int d = 0; d < HD; d += 4) {
            float4 v = *(const float4*)&qrow[d];
            q[d] = v.x; q[d+1] = v.y; q[d+2] = v.z; q[d+3] = v.w;
        }
    }

    float o[HD];
    #pragma unroll
    for (int d = 0; d < HD; d++) o[d] = 0.f;
    float m = -1e30f, l = 0.f;

    const int kend = q0 + AT_BM;           // keys < kend are all we need (causal)
    for (int k0 = 0; k0 < kend; k0 += AT_BN) {
        // cooperative K/V tile load: 32 rows x 16 float4 = 512 float4, 128 threads -> 4 each
        #pragma unroll
        for (int i = 0; i < 4; i++) {
            const int idx = tid + i * 128;
            const int r   = idx >> 4;
            const int c4  = idx & 15;
            const size_t base = (size_t)(b * Tseq + k0 + r) * C3 + h * HD + c4 * 4;
            *(float4*)&Ks[r][c4 * 4] = *(const float4*)&qkv[base + Cdim];
            *(float4*)&Vs[r][c4 * 4] = *(const float4*)&qkv[base + 2 * Cdim];
        }
        __syncthreads();

        // pass 1: scores + tile max
        float tile_max = -1e30f;
        #pragma unroll 4
        for (int j = 0; j < AT_BN; j++) {
            float s = 0.f;
            #pragma unroll
            for (int d = 0; d < HD; d += 4) {
                float4 kv = *(const float4*)&Ks[j][d];
                s = fmaf(q[d],   kv.x, s);
                s = fmaf(q[d+1], kv.y, s);
                s = fmaf(q[d+2], kv.z, s);
                s = fmaf(q[d+3], kv.w, s);
            }
            s *= scale;
            if (k0 + j > qi) s = -1e30f;   // causal mask
            Ss[j][tid] = s;
            tile_max = fmaxf(tile_max, s);
        }

        const float mnew = fmaxf(m, tile_max);
        const float corr = __expf(m - mnew);
        l *= corr;
        #pragma unroll
        for (int d = 0; d < HD; d++) o[d] *= corr;

        // pass 2: exp + accumulate into o
        #pragma unroll 4
        for (int j = 0; j < AT_BN; j++) {
            const float p = __expf(Ss[j][tid] - mnew);
            l += p;
            #pragma unroll
            for (int d = 0; d < HD; d += 4) {
                float4 vv = *(const float4*)&Vs[j][d];
                o[d]   = fmaf(p, vv.x, o[d]);
                o[d+1] = fmaf(p, vv.y, o[d+1]);
                o[d+2] = fmaf(p, vv.z, o[d+2]);
                o[d+3] = fmaf(p, vv.w, o[d+3]);
            }
        }
        m = mnew;
        __syncthreads();
    }

    const float inv = 1.f / l;
    float* yrow = y + ((size_t)(b * Tseq + qi) * Cdim) + h * HD;
    #pragma unroll
    for (int d = 0; d < HD; d += 4) {
        float4 ov;
        ov.x = o[d]   * inv;
        ov.y = o[d+1] * inv;
        ov.z = o[d+2] * inv;
        ov.w = o[d+3] * inv;
        *(float4*)&yrow[d] = ov;
    }
}

// ---------------- launch ----------------
extern "C" void kernel_launch(void* const* d_in, const int* in_sizes, int n_in,
                              void* d_out, int out_size)
{
    const float* x     = (const float*)d_in[0];
    const float* qkv_w = (const float*)d_in[1];
    const float* qkv_b = (const float*)d_in[2];
    const float* out_w = (const float*)d_in[3];
    const float* out_b = (const float*)d_in[4];
    float* out = (float*)d_out;

    float *qkv_p, *y_p;
    cudaGetSymbolAddress((void**)&qkv_p, g_qkv);
    cudaGetSymbolAddress((void**)&y_p,   g_y);

    const int M = Bsz * Tseq;   // 8192

    // 1) QKV projection: [8192,768] @ [768,2304] + bias
    gemm_bias_kernel<<<dim3(C3 / GBN, M / GBM), 256>>>(x, qkv_w, qkv_b, qkv_p, M, C3, Cdim);

    // 2) causal multi-head attention
    attn_kernel<<<dim3(Tseq / AT_BM, Bsz * Hn), 128>>>(qkv_p, y_p);

    // 3) output projection: [8192,768] @ [768,768] + bias
    gemm_bias_kernel<<<dim3(Cdim / GBN, M / GBM), 256>>>(y_p, out_w, out_b, out, M, Cdim, Cdim);
}

// round 3
// speedup vs baseline: 1.2048x; 1.2048x over previous
#include <cuda_runtime.h>
#include <cuda_bf16.h>
#include <cstdint>
#include <math.h>

#define Bsz 2
#define Tseq 4096
#define Cdim 768
#define Hn 12
#define HD 64
#define C3 (3*Cdim)
#define Mrows (Bsz*Tseq)   // 8192

// ---------------- scratch (no allocs allowed) ----------------
__device__ __align__(16) float g_qkv[(size_t)Bsz * Tseq * C3];   // [B,T,3C]
__device__ __align__(16) float g_y  [(size_t)Bsz * Tseq * Cdim]; // [B,T,C]
__device__ __align__(16) __nv_bfloat16 g_xh[(size_t)Mrows * Cdim];
__device__ __align__(16) __nv_bfloat16 g_xl[(size_t)Mrows * Cdim];
__device__ __align__(16) __nv_bfloat16 g_yh[(size_t)Mrows * Cdim];
__device__ __align__(16) __nv_bfloat16 g_yl[(size_t)Mrows * Cdim];
__device__ __align__(16) __nv_bfloat16 g_wqh[(size_t)C3 * Cdim];   // qkv_w^T  [N,K]
__device__ __align__(16) __nv_bfloat16 g_wql[(size_t)C3 * Cdim];
__device__ __align__(16) __nv_bfloat16 g_woh[(size_t)Cdim * Cdim]; // out_w^T  [N,K]
__device__ __align__(16) __nv_bfloat16 g_wol[(size_t)Cdim * Cdim];

// ================= portable PTX helpers (no sm_103a-only features) =================
__device__ __forceinline__ uint32_t smem_u32(const void* p) {
    uint32_t a;
    asm("{ .reg .u64 t; cvta.to.shared.u64 t, %1; cvt.u32.u64 %0, t; }" : "=r"(a) : "l"(p));
    return a;
}
#define CP_ASYNC16(dst, src) \
    asm volatile("cp.async.cg.shared.global [%0], [%1], 16;" :: "r"(dst), "l"(src) : "memory")
#define CP_COMMIT() asm volatile("cp.async.commit_group;" ::: "memory")
#define CP_WAIT(n)  asm volatile("cp.async.wait_group %0;" :: "n"(n) : "memory")

__device__ __forceinline__ void ldsm_x4(uint32_t& r0, uint32_t& r1, uint32_t& r2, uint32_t& r3,
                                        uint32_t addr) {
    asm volatile("ldmatrix.sync.aligned.m8n8.x4.shared.b16 {%0,%1,%2,%3}, [%4];"
                 : "=r"(r0), "=r"(r1), "=r"(r2), "=r"(r3) : "r"(addr));
}
__device__ __forceinline__ void mma16816(float* d, const uint32_t* a, const uint32_t* b) {
    asm volatile(
        "mma.sync.aligned.m16n8k16.row.col.f32.bf16.bf16.f32 "
        "{%0,%1,%2,%3}, {%4,%5,%6,%7}, {%8,%9}, {%0,%1,%2,%3};"
        : "+f"(d[0]), "+f"(d[1]), "+f"(d[2]), "+f"(d[3])
        : "r"(a[0]), "r"(a[1]), "r"(a[2]), "r"(a[3]), "r"(b[0]), "r"(b[1]));
}

// ================= fp32 -> bf16 hi/lo split (elementwise) =================
__global__ __launch_bounds__(256)
void split_kernel(const float* __restrict__ in, __nv_bfloat16* __restrict__ hi,
                  __nv_bfloat16* __restrict__ lo, int n4)
{
    int i4 = blockIdx.x * blockDim.x + threadIdx.x;
    if (i4 >= n4) return;
    float4 v = ((const float4*)in)[i4];
    float vv[4] = {v.x, v.y, v.z, v.w};
    __nv_bfloat16 h[4], l[4];
    #pragma unroll
    for (int j = 0; j < 4; j++) {
        h[j] = __float2bfloat16(vv[j]);
        l[j] = __float2bfloat16(vv[j] - __bfloat162float(h[j]));
    }
    ((uint2*)hi)[i4] = *(uint2*)h;
    ((uint2*)lo)[i4] = *(uint2*)l;
}

// ============ fp32 W[K,N] -> bf16 hi/lo transposed [N,K] ============
__global__ __launch_bounds__(256)
void splitT_kernel(const float* __restrict__ W, __nv_bfloat16* __restrict__ Th,
                   __nv_bfloat16* __restrict__ Tl, int K, int N)
{
    __shared__ float t[32][33];
    const int n0 = blockIdx.x * 32, k0 = blockIdx.y * 32;
    const int tx = threadIdx.x & 31, ty = (threadIdx.x >> 5);  // 32 x 8
    #pragma unroll
    for (int j = 0; j < 4; j++)
        t[ty + j*8][tx] = W[(size_t)(k0 + ty + j*8) * N + n0 + tx];
    __syncthreads();
    #pragma unroll
    for (int j = 0; j < 4; j++) {
        float v = t[tx][ty + j*8];
        __nv_bfloat16 h = __float2bfloat16(v);
        __nv_bfloat16 l = __float2bfloat16(v - __bfloat162float(h));
        size_t oidx = (size_t)(n0 + ty + j*8) * K + k0 + tx;
        Th[oidx] = h;
        Tl[oidx] = l;
    }
}

// ================= warp-MMA split-bf16 GEMM =================
// C[M,N] = (Ah+Al)[M,K] @ (Bh+Bl)^T + bias, B given as [N,K] (K-major).
// block tile 128x128, K-step 32, 8 warps (4m x 2n), each warp 32x64.
#define GBM 128
#define GBN 128
#define GBK 32
#define GPAD 40   // bf16 per smem row (80B) -> conflict-free ldmatrix
#define GBUF (128*GPAD*2)  // bytes per buffer per operand

__global__ __launch_bounds__(256)
void gemm_mma(const __nv_bfloat16* __restrict__ Ah, const __nv_bfloat16* __restrict__ Al,
              const __nv_bfloat16* __restrict__ Bh, const __nv_bfloat16* __restrict__ Bl,
              const float* __restrict__ bias, float* __restrict__ C,
              int M, int N, int K)
{
    __shared__ __align__(16) __nv_bfloat16 As[2][128][GPAD];
    __shared__ __align__(16) __nv_bfloat16 Bs[2][128][GPAD];

    const int tid  = threadIdx.x;
    const int lane = tid & 31;
    const int wid  = tid >> 5;
    const int wm   = wid & 3;          // 0..3 -> m offset wm*32
    const int wn   = wid >> 2;         // 0..1 -> n offset wn*64
    const int rowBase = blockIdx.y * GBM;
    const int colBase = blockIdx.x * GBN;

    const uint32_t asBase = smem_u32(As);
    const uint32_t bsBase = smem_u32(Bs);

    // cp.async destination mapping: chunk c in 0..511 -> row c>>2, 8-bf16 chunk c&3
    const int c0 = tid, c1 = tid + 256;
    const int ar0 = c0 >> 2, ac0 = (c0 & 3) * 8;
    const int ar1 = c1 >> 2, ac1 = (c1 & 3) * 8;
    const uint32_t ad0 = (uint32_t)(ar0 * GPAD + ac0) * 2;
    const uint32_t ad1 = (uint32_t)(ar1 * GPAD + ac1) * 2;

    // ldmatrix per-lane addresses (byte offsets within a buffer)
    const int mat = lane >> 3, r8 = lane & 7;
    uint32_t aAddr[2], bAddr[4];
    #pragma unroll
    for (int mt = 0; mt < 2; mt++) {
        int row = wm * 32 + mt * 16 + (mat & 1) * 8 + r8;
        int col = (mat >> 1) * 8;
        aAddr[mt] = asBase + (uint32_t)(row * GPAD + col) * 2;
    }
    #pragma unroll
    for (int nt2 = 0; nt2 < 4; nt2++) {
        int row = wn * 64 + nt2 * 16 + (mat >> 1) * 8 + r8;
        int col = (mat & 1) * 8;
        bAddr[nt2] = bsBase + (uint32_t)(row * GPAD + col) * 2;
    }

    float acc[2][8][4];
    #pragma unroll
    for (int i = 0; i < 2; i++)
        #pragma unroll
        for (int j = 0; j < 8; j++)
            #pragma unroll
            for (int q = 0; q < 4; q++) acc[i][j][q] = 0.f;

    const int KC  = K / GBK;      // chunks per pass
    const int TOT = 3 * KC;       // 3 passes: hh, hl, lh

    auto issue_tile = [&](int it) {
        const int buf = it & 1;
        const int p   = it / KC;
        const int kc  = it % KC;
        const __nv_bfloat16* Asrc = (p == 2) ? Al : Ah;
        const __nv_bfloat16* Bsrc = (p == 1) ? Bl : Bh;
        const uint32_t bufOff = (uint32_t)buf * GBUF;
        CP_ASYNC16(asBase + bufOff + ad0, Asrc + (size_t)(rowBase + ar0) * K + kc * GBK + ac0);
        CP_ASYNC16(asBase + bufOff + ad1, Asrc + (size_t)(rowBase + ar1) * K + kc * GBK + ac1);
        CP_ASYNC16(bsBase + bufOff + ad0, Bsrc + (size_t)(colBase + ar0) * K + kc * GBK + ac0);
        CP_ASYNC16(bsBase + bufOff + ad1, Bsrc + (size_t)(colBase + ar1) * K + kc * GBK + ac1);
        CP_COMMIT();
    };

    issue_tile(0);

    for (int it = 0; it < TOT; ++it) {
        if (it + 1 < TOT) { issue_tile(it + 1); CP_WAIT(1); }
        else              { CP_WAIT(0); }
        __syncthreads();

        const uint32_t bufOff = (uint32_t)(it & 1) * GBUF;
        #pragma unroll
        for (int kk = 0; kk < 2; kk++) {           // two k16 halves of the 32-chunk
            uint32_t af[2][4], bf[8][2];
            #pragma unroll
            for (int mt = 0; mt < 2; mt++)
                ldsm_x4(af[mt][0], af[mt][1], af[mt][2], af[mt][3],
                        aAddr[mt] + bufOff + kk * 32);
            #pragma unroll
            for (int nt2 = 0; nt2 < 4; nt2++) {
                uint32_t r0, r1, r2, r3;
                ldsm_x4(r0, r1, r2, r3, bAddr[nt2] + bufOff + kk * 32);
                bf[nt2*2][0] = r0; bf[nt2*2][1] = r1;
                bf[nt2*2+1][0] = r2; bf[nt2*2+1][1] = r3;
            }
            #pragma unroll
            for (int mt = 0; mt < 2; mt++)
                #pragma unroll
                for (int nt = 0; nt < 8; nt++)
                    mma16816(acc[mt][nt], af[mt], bf[nt]);
        }
        __syncthreads();
    }

    // epilogue: fp32 accumulators + bias -> C
    const int g = lane >> 2, t = lane & 3;
    #pragma unroll
    for (int mt = 0; mt < 2; mt++) {
        #pragma unroll
        for (int nt = 0; nt < 8; nt++) {
            const int col = colBase + wn * 64 + nt * 8 + t * 2;
            const float b0 = bias[col], b1 = bias[col + 1];
            const int row0 = rowBase + wm * 32 + mt * 16 + g;
            float2 v0 = { acc[mt][nt][0] + b0, acc[mt][nt][1] + b1 };
            float2 v1 = { acc[mt][nt][2] + b0, acc[mt][nt][3] + b1 };
            *(float2*)&C[(size_t)row0 * N + col]       = v0;
            *(float2*)&C[(size_t)(row0 + 8) * N + col] = v1;
        }
    }
}

// ---------------- causal flash attention, fp32, 1 thread = 1 query row ----------------
#define AT_BM 128
#define AT_BN 32

__global__ __launch_bounds__(128)
void attn_kernel(const float* __restrict__ qkv, float* __restrict__ y)
{
    const int bh = blockIdx.y;
    const int b  = bh / Hn;
    const int h  = bh % Hn;
    const int q0 = blockIdx.x * AT_BM;
    const int tid = threadIdx.x;
    const int qi  = q0 + tid;
    const float scale = 0.125f;

    __shared__ float Ks[AT_BN][HD];
    __shared__ float Vs[AT_BN][HD];
    __shared__ float Ss[AT_BN][AT_BM];

    float q[HD];
    {
        const float* qrow = qkv + ((size_t)(b * Tseq + qi) * C3) + h * HD;
        #pragma unroll
        for (int d = 0; d < HD; d += 4) {
            float4 v = *(const float4*)&qrow[d];
            q[d] = v.x; q[d+1] = v.y; q[d+2] = v.z; q[d+3] = v.w;
        }
    }

    float o[HD];
    #pragma unroll
    for (int d = 0; d < HD; d++) o[d] = 0.f;
    float m = -1e30f, l = 0.f;

    const int kend = q0 + AT_BM;
    for (int k0 = 0; k0 < kend; k0 += AT_BN) {
        #pragma unroll
        for (int i = 0; i < 4; i++) {
            const int idx = tid + i * 128;
            const int r   = idx >> 4;
            const int c4  = idx & 15;
            const size_t base = (size_t)(b * Tseq + k0 + r) * C3 + h * HD + c4 * 4;
            *(float4*)&Ks[r][c4 * 4] = *(const float4*)&qkv[base + Cdim];
            *(float4*)&Vs[r][c4 * 4] = *(const float4*)&qkv[base + 2 * Cdim];
        }
        __syncthreads();

        float tile_max = -1e30f;
        #pragma unroll 4
        for (int j = 0; j < AT_BN; j++) {
            float s = 0.f;
            #pragma unroll
            for (int d = 0; d < HD; d += 4) {
                float4 kv = *(const float4*)&Ks[j][d];
                s = fmaf(q[d],   kv.x, s);
                s = fmaf(q[d+1], kv.y, s);
                s = fmaf(q[d+2], kv.z, s);
                s = fmaf(q[d+3], kv.w, s);
            }
            s *= scale;
            if (k0 + j > qi) s = -1e30f;
            Ss[j][tid] = s;
            tile_max = fmaxf(tile_max, s);
        }

        const float mnew = fmaxf(m, tile_max);
        const float corr = __expf(m - mnew);
        l *= corr;
        #pragma unroll
        for (int d = 0; d < HD; d++) o[d] *= corr;

        #pragma unroll 4
        for (int j = 0; j < AT_BN; j++) {
            const float p = __expf(Ss[j][tid] - mnew);
            l += p;
            #pragma unroll
            for (int d = 0; d < HD; d += 4) {
                float4 vv = *(const float4*)&Vs[j][d];
                o[d]   = fmaf(p, vv.x, o[d]);
                o[d+1] = fmaf(p, vv.y, o[d+1]);
                o[d+2] = fmaf(p, vv.z, o[d+2]);
                o[d+3] = fmaf(p, vv.w, o[d+3]);
            }
        }
        m = mnew;
        __syncthreads();
    }

    const float inv = 1.f / l;
    float* yrow = y + ((size_t)(b * Tseq + qi) * Cdim) + h * HD;
    #pragma unroll
    for (int d = 0; d < HD; d += 4) {
        float4 ov;
        ov.x = o[d]   * inv;
        ov.y = o[d+1] * inv;
        ov.z = o[d+2] * inv;
        ov.w = o[d+3] * inv;
        *(float4*)&yrow[d] = ov;
    }
}

// ---------------- launch ----------------
extern "C" void kernel_launch(void* const* d_in, const int* in_sizes, int n_in,
                              void* d_out, int out_size)
{
    const float* x     = (const float*)d_in[0];
    const float* qkv_w = (const float*)d_in[1];
    const float* qkv_b = (const float*)d_in[2];
    const float* out_w = (const float*)d_in[3];
    const float* out_b = (const float*)d_in[4];
    float* out = (float*)d_out;

    float *qkv_p, *y_p;
    __nv_bfloat16 *xh, *xl, *yh, *yl, *wqh, *wql, *woh, *wol;
    cudaGetSymbolAddress((void**)&qkv_p, g_qkv);
    cudaGetSymbolAddress((void**)&y_p,   g_y);
    cudaGetSymbolAddress((void**)&xh, g_xh);
    cudaGetSymbolAddress((void**)&xl, g_xl);
    cudaGetSymbolAddress((void**)&yh, g_yh);
    cudaGetSymbolAddress((void**)&yl, g_yl);
    cudaGetSymbolAddress((void**)&wqh, g_wqh);
    cudaGetSymbolAddress((void**)&wql, g_wql);
    cudaGetSymbolAddress((void**)&woh, g_woh);
    cudaGetSymbolAddress((void**)&wol, g_wol);

    const int M = Mrows;   // 8192

    {
        int n4 = (M * Cdim) / 4;
        split_kernel<<<(n4 + 255) / 256, 256>>>(x, xh, xl, n4);
    }
    splitT_kernel<<<dim3(C3 / 32, Cdim / 32), 256>>>(qkv_w, wqh, wql, Cdim, C3);
    splitT_kernel<<<dim3(Cdim / 32, Cdim / 32), 256>>>(out_w, woh, wol, Cdim, Cdim);

    // 1) QKV projection (tensor cores): [8192,768] @ [768,2304] + bias
    gemm_mma<<<dim3(C3 / GBN, M / GBM), 256>>>(xh, xl, wqh, wql, qkv_b, qkv_p, M, C3, Cdim);

    // 2) causal multi-head attention (fp32)
    attn_kernel<<<dim3(Tseq / AT_BM, Bsz * Hn), 128>>>(qkv_p, y_p);

    {
        int n4 = (M * Cdim) / 4;
        split_kernel<<<(n4 + 255) / 256, 256>>>(y_p, yh, yl, n4);
    }

    // 3) output projection (tensor cores): [8192,768] @ [768,768] + bias
    gemm_mma<<<dim3(Cdim / GBN, M / GBM), 256>>>(yh, yl, woh, wol, out_b, out, M, Cdim, Cdim);
}

// round 4
// speedup vs baseline: 3.5665x; 2.9604x over previous
#include <cuda_runtime.h>
#include <cuda_bf16.h>
#include <cstdint>
#include <math.h>

#define Bsz 2
#define Tseq 4096
#define Cdim 768
#define Hn 12
#define HD 64
#define C3 (3*Cdim)
#define Mrows (Bsz*Tseq)   // 8192

// ---------------- scratch (no allocs allowed) ----------------
__device__ __align__(16) __nv_bfloat16 g_xh[(size_t)Mrows * Cdim];
__device__ __align__(16) __nv_bfloat16 g_xl[(size_t)Mrows * Cdim];
__device__ __align__(16) __nv_bfloat16 g_qkvh[(size_t)Mrows * C3];
__device__ __align__(16) __nv_bfloat16 g_qkvl[(size_t)Mrows * C3];
__device__ __align__(16) __nv_bfloat16 g_yh[(size_t)Mrows * Cdim];
__device__ __align__(16) __nv_bfloat16 g_yl[(size_t)Mrows * Cdim];
__device__ __align__(16) __nv_bfloat16 g_wqh[(size_t)C3 * Cdim];   // qkv_w^T  [N,K]
__device__ __align__(16) __nv_bfloat16 g_wql[(size_t)C3 * Cdim];
__device__ __align__(16) __nv_bfloat16 g_woh[(size_t)Cdim * Cdim]; // out_w^T  [N,K]
__device__ __align__(16) __nv_bfloat16 g_wol[(size_t)Cdim * Cdim];

// ================= portable PTX helpers =================
__device__ __forceinline__ uint32_t smem_u32(const void* p) {
    uint32_t a;
    asm("{ .reg .u64 t; cvta.to.shared.u64 t, %1; cvt.u32.u64 %0, t; }" : "=r"(a) : "l"(p));
    return a;
}
#define CP_ASYNC16(dst, src) \
    asm volatile("cp.async.cg.shared.global [%0], [%1], 16;" :: "r"(dst), "l"(src) : "memory")
#define CP_COMMIT() asm volatile("cp.async.commit_group;" ::: "memory")
#define CP_WAIT(n)  asm volatile("cp.async.wait_group %0;" :: "n"(n) : "memory")

__device__ __forceinline__ void ldsm_x4(uint32_t& r0, uint32_t& r1, uint32_t& r2, uint32_t& r3,
                                        uint32_t addr) {
    asm volatile("ldmatrix.sync.aligned.m8n8.x4.shared.b16 {%0,%1,%2,%3}, [%4];"
                 : "=r"(r0), "=r"(r1), "=r"(r2), "=r"(r3) : "r"(addr));
}
__device__ __forceinline__ void ldsm_x4_t(uint32_t& r0, uint32_t& r1, uint32_t& r2, uint32_t& r3,
                                          uint32_t addr) {
    asm volatile("ldmatrix.sync.aligned.m8n8.x4.trans.shared.b16 {%0,%1,%2,%3}, [%4];"
                 : "=r"(r0), "=r"(r1), "=r"(r2), "=r"(r3) : "r"(addr));
}
__device__ __forceinline__ void mma16816(float* d, const uint32_t* a, const uint32_t* b) {
    asm volatile(
        "mma.sync.aligned.m16n8k16.row.col.f32.bf16.bf16.f32 "
        "{%0,%1,%2,%3}, {%4,%5,%6,%7}, {%8,%9}, {%0,%1,%2,%3};"
        : "+f"(d[0]), "+f"(d[1]), "+f"(d[2]), "+f"(d[3])
        : "r"(a[0]), "r"(a[1]), "r"(a[2]), "r"(a[3]), "r"(b[0]), "r"(b[1]));
}
// pack two f32 -> bf16x2 (lo in bits [15:0], hi in [31:16])
__device__ __forceinline__ uint32_t packbf(float lo, float hi) {
    uint32_t d;
    asm("cvt.rn.bf16x2.f32 %0, %1, %2;" : "=r"(d) : "f"(hi), "f"(lo));
    return d;
}
__device__ __forceinline__ float bflo(uint32_t u) { return __uint_as_float(u << 16); }
__device__ __forceinline__ float bfhi(uint32_t u) { return __uint_as_float(u & 0xffff0000u); }

// ================= fp32 -> bf16 hi/lo split (elementwise) =================
__global__ __launch_bounds__(256)
void split_kernel(const float* __restrict__ in, __nv_bfloat16* __restrict__ hi,
                  __nv_bfloat16* __restrict__ lo, int n4)
{
    int i4 = blockIdx.x * blockDim.x + threadIdx.x;
    if (i4 >= n4) return;
    float4 v = ((const float4*)in)[i4];
    float vv[4] = {v.x, v.y, v.z, v.w};
    uint32_t h[2], l[2];
    #pragma unroll
    for (int j = 0; j < 2; j++) {
        h[j] = packbf(vv[j*2], vv[j*2+1]);
        l[j] = packbf(vv[j*2] - bflo(h[j]), vv[j*2+1] - bfhi(h[j]));
    }
    ((uint2*)hi)[i4] = make_uint2(h[0], h[1]);
    ((uint2*)lo)[i4] = make_uint2(l[0], l[1]);
}

// ============ fp32 W[K,N] -> bf16 hi/lo transposed [N,K] ============
__global__ __launch_bounds__(256)
void splitT_kernel(const float* __restrict__ W, __nv_bfloat16* __restrict__ Th,
                   __nv_bfloat16* __restrict__ Tl, int K, int N)
{
    __shared__ float t[32][33];
    const int n0 = blockIdx.x * 32, k0 = blockIdx.y * 32;
    const int tx = threadIdx.x & 31, ty = (threadIdx.x >> 5);
    #pragma unroll
    for (int j = 0; j < 4; j++)
        t[ty + j*8][tx] = W[(size_t)(k0 + ty + j*8) * N + n0 + tx];
    __syncthreads();
    #pragma unroll
    for (int j = 0; j < 4; j++) {
        float v = t[tx][ty + j*8];
        __nv_bfloat16 h = __float2bfloat16(v);
        __nv_bfloat16 l = __float2bfloat16(v - __bfloat162float(h));
        size_t oidx = (size_t)(n0 + ty + j*8) * K + k0 + tx;
        Th[oidx] = h;
        Tl[oidx] = l;
    }
}

// ================= warp-MMA split-bf16 GEMM =================
#define GBM 128
#define GBN 128
#define GBK 32
#define GPAD 40
#define GBUF (128*GPAD*2)

template<bool SPLIT_OUT>
__global__ __launch_bounds__(256)
void gemm_mma(const __nv_bfloat16* __restrict__ Ah, const __nv_bfloat16* __restrict__ Al,
              const __nv_bfloat16* __restrict__ Bh, const __nv_bfloat16* __restrict__ Bl,
              const float* __restrict__ bias, float* __restrict__ C,
              __nv_bfloat16* __restrict__ Ch, __nv_bfloat16* __restrict__ Cl,
              int M, int N, int K)
{
    __shared__ __align__(16) __nv_bfloat16 As[2][128][GPAD];
    __shared__ __align__(16) __nv_bfloat16 Bs[2][128][GPAD];

    const int tid  = threadIdx.x;
    const int lane = tid & 31;
    const int wid  = tid >> 5;
    const int wm   = wid & 3;
    const int wn   = wid >> 2;
    const int rowBase = blockIdx.y * GBM;
    const int colBase = blockIdx.x * GBN;

    const uint32_t asBase = smem_u32(As);
    const uint32_t bsBase = smem_u32(Bs);

    const int c0 = tid, c1 = tid + 256;
    const int ar0 = c0 >> 2, ac0 = (c0 & 3) * 8;
    const int ar1 = c1 >> 2, ac1 = (c1 & 3) * 8;
    const uint32_t ad0 = (uint32_t)(ar0 * GPAD + ac0) * 2;
    const uint32_t ad1 = (uint32_t)(ar1 * GPAD + ac1) * 2;

    const int mat = lane >> 3, r8 = lane & 7;
    uint32_t aAddr[2], bAddr[4];
    #pragma unroll
    for (int mt = 0; mt < 2; mt++) {
        int row = wm * 32 + mt * 16 + (mat & 1) * 8 + r8;
        int col = (mat >> 1) * 8;
        aAddr[mt] = asBase + (uint32_t)(row * GPAD + col) * 2;
    }
    #pragma unroll
    for (int nt2 = 0; nt2 < 4; nt2++) {
        int row = wn * 64 + nt2 * 16 + (mat >> 1) * 8 + r8;
        int col = (mat & 1) * 8;
        bAddr[nt2] = bsBase + (uint32_t)(row * GPAD + col) * 2;
    }

    float acc[2][8][4];
    #pragma unroll
    for (int i = 0; i < 2; i++)
        #pragma unroll
        for (int j = 0; j < 8; j++)
            #pragma unroll
            for (int q = 0; q < 4; q++) acc[i][j][q] = 0.f;

    const int KC  = K / GBK;
    const int TOT = 3 * KC;

    auto issue_tile = [&](int it) {
        const int buf = it & 1;
        const int p   = it / KC;
        const int kc  = it % KC;
        const __nv_bfloat16* Asrc = (p == 2) ? Al : Ah;
        const __nv_bfloat16* Bsrc = (p == 1) ? Bl : Bh;
        const uint32_t bufOff = (uint32_t)buf * GBUF;
        CP_ASYNC16(asBase + bufOff + ad0, Asrc + (size_t)(rowBase + ar0) * K + kc * GBK + ac0);
        CP_ASYNC16(asBase + bufOff + ad1, Asrc + (size_t)(rowBase + ar1) * K + kc * GBK + ac1);
        CP_ASYNC16(bsBase + bufOff + ad0, Bsrc + (size_t)(colBase + ar0) * K + kc * GBK + ac0);
        CP_ASYNC16(bsBase + bufOff + ad1, Bsrc + (size_t)(colBase + ar1) * K + kc * GBK + ac1);
        CP_COMMIT();
    };

    issue_tile(0);

    for (int it = 0; it < TOT; ++it) {
        if (it + 1 < TOT) { issue_tile(it + 1); CP_WAIT(1); }
        else              { CP_WAIT(0); }
        __syncthreads();

        const uint32_t bufOff = (uint32_t)(it & 1) * GBUF;
        #pragma unroll
        for (int kk = 0; kk < 2; kk++) {
            uint32_t af[2][4], bf[8][2];
            #pragma unroll
            for (int mt = 0; mt < 2; mt++)
                ldsm_x4(af[mt][0], af[mt][1], af[mt][2], af[mt][3],
                        aAddr[mt] + bufOff + kk * 32);
            #pragma unroll
            for (int nt2 = 0; nt2 < 4; nt2++) {
                uint32_t r0, r1, r2, r3;
                ldsm_x4(r0, r1, r2, r3, bAddr[nt2] + bufOff + kk * 32);
                bf[nt2*2][0] = r0; bf[nt2*2][1] = r1;
                bf[nt2*2+1][0] = r2; bf[nt2*2+1][1] = r3;
            }
            #pragma unroll
            for (int mt = 0; mt < 2; mt++)
                #pragma unroll
                for (int nt = 0; nt < 8; nt++)
                    mma16816(acc[mt][nt], af[mt], bf[nt]);
        }
        __syncthreads();
    }

    const int g = lane >> 2, t = lane & 3;
    #pragma unroll
    for (int mt = 0; mt < 2; mt++) {
        #pragma unroll
        for (int nt = 0; nt < 8; nt++) {
            const int col = colBase + wn * 64 + nt * 8 + t * 2;
            const float b0 = bias[col], b1 = bias[col + 1];
            const int row0 = rowBase + wm * 32 + mt * 16 + g;
            float v0 = acc[mt][nt][0] + b0, v1 = acc[mt][nt][1] + b1;
            float v2 = acc[mt][nt][2] + b0, v3 = acc[mt][nt][3] + b1;
            if (SPLIT_OUT) {
                uint32_t h0 = packbf(v0, v1);
                uint32_t l0 = packbf(v0 - bflo(h0), v1 - bfhi(h0));
                uint32_t h1 = packbf(v2, v3);
                uint32_t l1 = packbf(v2 - bflo(h1), v3 - bfhi(h1));
                *(uint32_t*)(Ch + (size_t)row0 * N + col)       = h0;
                *(uint32_t*)(Cl + (size_t)row0 * N + col)       = l0;
                *(uint32_t*)(Ch + (size_t)(row0 + 8) * N + col) = h1;
                *(uint32_t*)(Cl + (size_t)(row0 + 8) * N + col) = l1;
            } else {
                *(float2*)&C[(size_t)row0 * N + col]       = make_float2(v0, v1);
                *(float2*)&C[(size_t)(row0 + 8) * N + col] = make_float2(v2, v3);
            }
        }
    }
}

// ================= tensor-core causal flash attention (split bf16) =================
// CTA: 128 queries, 8 warps x 16 rows. K-tiles of 64. D = 64.
#define PADK 72                       // bf16 per smem row (144B stride)
#define TILEB (64*PADK*2)             // 9216 B per 64x64 tile
#define BUFB  (4*TILEB)               // Kh,Kl,Vh,Vl = 36864 B per buffer
#define ATT_SMEM (2*BUFB)             // 73728 B
#define ESC 0.18033688f               // 0.125 * log2(e)

__global__ __launch_bounds__(256)
void attn_mma(const __nv_bfloat16* __restrict__ qkvh, const __nv_bfloat16* __restrict__ qkvl,
              __nv_bfloat16* __restrict__ yh, __nv_bfloat16* __restrict__ yl)
{
    extern __shared__ __align__(16) char sm[];
    const uint32_t smBase = smem_u32(sm);

    const int tid  = threadIdx.x;
    const int lane = tid & 31;
    const int wm   = tid >> 5;          // warp id 0..7 -> rows wm*16
    const int bh = blockIdx.y;
    const int b  = bh / Hn;
    const int h  = bh % Hn;
    const int q0 = (gridDim.x - 1 - blockIdx.x) * 128;   // big tiles first

    const int mat = lane >> 3, r8 = lane & 7;
    const int g = lane >> 2, t = lane & 3;

    // ---- stage Q (hi/lo) into buffer0 area, load A-fragments ----
    {
        #pragma unroll
        for (int i = 0; i < 8; i++) {
            const int idx = tid + i * 256;          // 2048 chunks
            const int half = idx >> 10;             // 0 = hi, 1 = lo
            const int r    = (idx >> 3) & 127;
            const int c8   = idx & 7;
            const uint32_t dst = smBase + half * 18432u + (uint32_t)(r * PADK + c8 * 8) * 2;
            const __nv_bfloat16* src = (half ? qkvl : qkvh)
                + (size_t)(b * Tseq + q0 + r) * C3 + h * HD + c8 * 8;
            CP_ASYNC16(dst, src);
        }
        CP_COMMIT();
        CP_WAIT(0);
        __syncthreads();
    }

    uint32_t qh[4][4], ql[4][4];
    {
        const uint32_t qrow = (uint32_t)(wm * 16 + (mat & 1) * 8 + r8);
        #pragma unroll
        for (int ks = 0; ks < 4; ks++) {
            const uint32_t off = (qrow * PADK + (uint32_t)(ks * 16 + (mat >> 1) * 8)) * 2;
            ldsm_x4(qh[ks][0], qh[ks][1], qh[ks][2], qh[ks][3], smBase + off);
            ldsm_x4(ql[ks][0], ql[ks][1], ql[ks][2], ql[ks][3], smBase + 18432u + off);
        }
    }
    __syncthreads();   // Q consumed; buffer0 reusable

    // ldmatrix offsets within a K/V tile
    uint32_t kOff[4], vOff[4];
    #pragma unroll
    for (int nt2 = 0; nt2 < 4; nt2++) {
        kOff[nt2] = (uint32_t)((nt2 * 16 + (mat >> 1) * 8 + r8) * PADK + (mat & 1) * 8) * 2;
        vOff[nt2] = (uint32_t)(((mat & 1) * 8 + r8) * PADK + nt2 * 16 + (mat >> 1) * 8) * 2;
    }

    const int nk = q0 / 64 + 2;

    auto fill = [&](int it) {
        const int k0 = it * 64;
        const uint32_t bufOff = (uint32_t)(it & 1) * BUFB;
        #pragma unroll
        for (int i = 0; i < 8; i++) {
            const int idx = tid + i * 256;       // 2048 chunks
            const int tile = idx >> 9;           // 0 Kh, 1 Kl, 2 Vh, 3 Vl
            const int r    = (idx >> 3) & 63;
            const int c8   = idx & 7;
            const uint32_t dst = smBase + bufOff + tile * TILEB
                               + (uint32_t)(r * PADK + c8 * 8) * 2;
            const size_t srow = (size_t)(b * Tseq + k0 + r) * C3 + h * HD + c8 * 8
                              + ((tile >> 1) ? 2 * Cdim : Cdim);
            const __nv_bfloat16* src = ((tile & 1) ? qkvl : qkvh) + srow;
            CP_ASYNC16(dst, src);
        }
        CP_COMMIT();
    };

    fill(0);
    if (nk > 1) fill(1);

    float O[8][4];
    #pragma unroll
    for (int nt = 0; nt < 8; nt++)
        #pragma unroll
        for (int q = 0; q < 4; q++) O[nt][q] = 0.f;
    float m0 = -1e30f, m1 = -1e30f, l0 = 0.f, l1 = 0.f;

    const int rowg0 = q0 + wm * 16 + g;       // rows handled by this lane
    const int rowg1 = rowg0 + 8;

    for (int it = 0; it < nk; ++it) {
        if (it + 1 < nk) { CP_WAIT(1); } else { CP_WAIT(0); }
        __syncthreads();

        const int k0 = it * 64;
        const uint32_t bufO = smBase + (uint32_t)(it & 1) * BUFB;

        // ---- S = (Qh+Ql)(Kh)^T + Qh(Kl)^T ----
        float S[8][4];
        #pragma unroll
        for (int nt = 0; nt < 8; nt++)
            #pragma unroll
            for (int q = 0; q < 4; q++) S[nt][q] = 0.f;

        #pragma unroll
        for (int ks = 0; ks < 4; ks++) {
            uint32_t kf[8][2];
            #pragma unroll
            for (int nt2 = 0; nt2 < 4; nt2++) {
                uint32_t r0, r1, r2, r3;
                ldsm_x4(r0, r1, r2, r3, bufO + kOff[nt2] + ks * 32);
                kf[nt2*2][0] = r0; kf[nt2*2][1] = r1;
                kf[nt2*2+1][0] = r2; kf[nt2*2+1][1] = r3;
            }
            #pragma unroll
            for (int nt = 0; nt < 8; nt++) mma16816(S[nt], qh[ks], kf[nt]);
            #pragma unroll
            for (int nt = 0; nt < 8; nt++) mma16816(S[nt], ql[ks], kf[nt]);
            #pragma unroll
            for (int nt2 = 0; nt2 < 4; nt2++) {
                uint32_t r0, r1, r2, r3;
                ldsm_x4(r0, r1, r2, r3, bufO + TILEB + kOff[nt2] + ks * 32);
                kf[nt2*2][0] = r0; kf[nt2*2][1] = r1;
                kf[nt2*2+1][0] = r2; kf[nt2*2+1][1] = r3;
            }
            #pragma unroll
            for (int nt = 0; nt < 8; nt++) mma16816(S[nt], qh[ks], kf[nt]);
        }

        // ---- causal mask (diagonal tiles only) ----
        if (k0 + 63 > q0 + wm * 16) {
            #pragma unroll
            for (int nt = 0; nt < 8; nt++) {
                const int c = k0 + nt * 8 + t * 2;
                if (c     > rowg0) S[nt][0] = -1e30f;
                if (c + 1 > rowg0) S[nt][1] = -1e30f;
                if (c     > rowg1) S[nt][2] = -1e30f;
                if (c + 1 > rowg1) S[nt][3] = -1e30f;
            }
        }

        // ---- online softmax ----
        float mx0 = -1e30f, mx1 = -1e30f;
        #pragma unroll
        for (int nt = 0; nt < 8; nt++) {
            mx0 = fmaxf(mx0, fmaxf(S[nt][0], S[nt][1]));
            mx1 = fmaxf(mx1, fmaxf(S[nt][2], S[nt][3]));
        }
        mx0 = fmaxf(mx0, __shfl_xor_sync(0xffffffffu, mx0, 1));
        mx0 = fmaxf(mx0, __shfl_xor_sync(0xffffffffu, mx0, 2));
        mx1 = fmaxf(mx1, __shfl_xor_sync(0xffffffffu, mx1, 1));
        mx1 = fmaxf(mx1, __shfl_xor_sync(0xffffffffu, mx1, 2));

        const float mn0 = fmaxf(m0, mx0);
        const float mn1 = fmaxf(m1, mx1);
        const float cr0 = exp2f((m0 - mn0) * ESC);
        const float cr1 = exp2f((m1 - mn1) * ESC);
        m0 = mn0; m1 = mn1;
        l0 *= cr0; l1 *= cr1;
        #pragma unroll
        for (int nt = 0; nt < 8; nt++) {
            O[nt][0] *= cr0; O[nt][1] *= cr0;
            O[nt][2] *= cr1; O[nt][3] *= cr1;
        }

        float rs0 = 0.f, rs1 = 0.f;
        #pragma unroll
        for (int nt = 0; nt < 8; nt++) {
            S[nt][0] = exp2f((S[nt][0] - mn0) * ESC);
            S[nt][1] = exp2f((S[nt][1] - mn0) * ESC);
            S[nt][2] = exp2f((S[nt][2] - mn1) * ESC);
            S[nt][3] = exp2f((S[nt][3] - mn1) * ESC);
            rs0 += S[nt][0] + S[nt][1];
            rs1 += S[nt][2] + S[nt][3];
        }
        rs0 += __shfl_xor_sync(0xffffffffu, rs0, 1);
        rs0 += __shfl_xor_sync(0xffffffffu, rs0, 2);
        rs1 += __shfl_xor_sync(0xffffffffu, rs1, 1);
        rs1 += __shfl_xor_sync(0xffffffffu, rs1, 2);
        l0 += rs0; l1 += rs1;

        // ---- P hi/lo fragments ----
        uint32_t phi[4][4], plo[4][4];
        #pragma unroll
        for (int kk = 0; kk < 4; kk++) {
            phi[kk][0] = packbf(S[2*kk][0],   S[2*kk][1]);
            phi[kk][1] = packbf(S[2*kk][2],   S[2*kk][3]);
            phi[kk][2] = packbf(S[2*kk+1][0], S[2*kk+1][1]);
            phi[kk][3] = packbf(S[2*kk+1][2], S[2*kk+1][3]);
            plo[kk][0] = packbf(S[2*kk][0]   - bflo(phi[kk][0]), S[2*kk][1]   - bfhi(phi[kk][0]));
            plo[kk][1] = packbf(S[2*kk][2]   - bflo(phi[kk][1]), S[2*kk][3]   - bfhi(phi[kk][1]));
            plo[kk][2] = packbf(S[2*kk+1][0] - bflo(phi[kk][2]), S[2*kk+1][1] - bfhi(phi[kk][2]));
            plo[kk][3] = packbf(S[2*kk+1][2] - bflo(phi[kk][3]), S[2*kk+1][3] - bfhi(phi[kk][3]));
        }

        // ---- O += (Ph+Pl) Vh + Ph Vl ----
        #pragma unroll
        for (int kk = 0; kk < 4; kk++) {
            uint32_t vf[8][2];
            #pragma unroll
            for (int nd2 = 0; nd2 < 4; nd2++) {
                uint32_t r0, r1, r2, r3;
                ldsm_x4_t(r0, r1, r2, r3, bufO + 2*TILEB + vOff[nd2] + kk * (PADK*16*2));
                vf[nd2*2][0] = r0; vf[nd2*2][1] = r1;
                vf[nd2*2+1][0] = r2; vf[nd2*2+1][1] = r3;
            }
            #pragma unroll
            for (int nd = 0; nd < 8; nd++) mma16816(O[nd], phi[kk], vf[nd]);
            #pragma unroll
            for (int nd = 0; nd < 8; nd++) mma16816(O[nd], plo[kk], vf[nd]);
            #pragma unroll
            for (int nd2 = 0; nd2 < 4; nd2++) {
                uint32_t r0, r1, r2, r3;
                ldsm_x4_t(r0, r1, r2, r3, bufO + 3*TILEB + vOff[nd2] + kk * (PADK*16*2));
                vf[nd2*2][0] = r0; vf[nd2*2][1] = r1;
                vf[nd2*2+1][0] = r2; vf[nd2*2+1][1] = r3;
            }
            #pragma unroll
            for (int nd = 0; nd < 8; nd++) mma16816(O[nd], phi[kk], vf[nd]);
        }

        __syncthreads();                         // all warps done with this buffer
        if (it + 2 < nk) fill(it + 2);
    }

    // ---- epilogue: normalize, split to bf16 hi/lo, store ----
    const float i0 = 1.f / l0, i1 = 1.f / l1;
    const size_t base0 = (size_t)(b * Tseq + rowg0) * Cdim + h * HD;
    const size_t base1 = (size_t)(b * Tseq + rowg1) * Cdim + h * HD;
    #pragma unroll
    for (int nt = 0; nt < 8; nt++) {
        const int col = nt * 8 + t * 2;
        float v0 = O[nt][0] * i0, v1 = O[nt][1] * i0;
        float v2 = O[nt][2] * i1, v3 = O[nt][3] * i1;
        uint32_t h0 = packbf(v0, v1);
        uint32_t L0 = packbf(v0 - bflo(h0), v1 - bfhi(h0));
        uint32_t h1 = packbf(v2, v3);
        uint32_t L1 = packbf(v2 - bflo(h1), v3 - bfhi(h1));
        *(uint32_t*)(yh + base0 + col) = h0;
        *(uint32_t*)(yl + base0 + col) = L0;
        *(uint32_t*)(yh + base1 + col) = h1;
        *(uint32_t*)(yl + base1 + col) = L1;
    }
}

// ---------------- launch ----------------
extern "C" void kernel_launch(void* const* d_in, const int* in_sizes, int n_in,
                              void* d_out, int out_size)
{
    const float* x     = (const float*)d_in[0];
    const float* qkv_w = (const float*)d_in[1];
    const float* qkv_b = (const float*)d_in[2];
    const float* out_w = (const float*)d_in[3];
    const float* out_b = (const float*)d_in[4];
    float* out = (float*)d_out;

    __nv_bfloat16 *xh, *xl, *qh, *ql, *yh, *yl, *wqh, *wql, *woh, *wol;
    cudaGetSymbolAddress((void**)&xh, g_xh);
    cudaGetSymbolAddress((void**)&xl, g_xl);
    cudaGetSymbolAddress((void**)&qh, g_qkvh);
    cudaGetSymbolAddress((void**)&ql, g_qkvl);
    cudaGetSymbolAddress((void**)&yh, g_yh);
    cudaGetSymbolAddress((void**)&yl, g_yl);
    cudaGetSymbolAddress((void**)&wqh, g_wqh);
    cudaGetSymbolAddress((void**)&wql, g_wql);
    cudaGetSymbolAddress((void**)&woh, g_woh);
    cudaGetSymbolAddress((void**)&wol, g_wol);

    cudaFuncSetAttribute(attn_mma, cudaFuncAttributeMaxDynamicSharedMemorySize, ATT_SMEM);

    const int M = Mrows;   // 8192

    {
        int n4 = (M * Cdim) / 4;
        split_kernel<<<(n4 + 255) / 256, 256>>>(x, xh, xl, n4);
    }
    splitT_kernel<<<dim3(C3 / 32, Cdim / 32), 256>>>(qkv_w, wqh, wql, Cdim, C3);
    splitT_kernel<<<dim3(Cdim / 32, Cdim / 32), 256>>>(out_w, woh, wol, Cdim, Cdim);

    // 1) QKV projection -> split bf16 qkv directly
    gemm_mma<true><<<dim3(C3 / GBN, M / GBM), 256>>>(xh, xl, wqh, wql, qkv_b,
                                                     nullptr, qh, ql, M, C3, Cdim);

    // 2) causal attention on tensor cores -> split bf16 y
    attn_mma<<<dim3(Tseq / 128, Bsz * Hn), 256, ATT_SMEM>>>(qh, ql, yh, yl);

    // 3) output projection -> fp32 out
    gemm_mma<false><<<dim3(Cdim / GBN, M / GBM), 256>>>(yh, yl, woh, wol, out_b,
                                                        out, nullptr, nullptr, M, Cdim, Cdim);
}

// round 5
// speedup vs baseline: 5.3964x; 1.5131x over previous
#include <cuda_runtime.h>
#include <cuda_fp16.h>
#include <cstdint>
#include <math.h>

#define Bsz 2
#define Tseq 4096
#define Cdim 768
#define Hn 12
#define HD 64
#define C3 (3*Cdim)
#define Mrows (Bsz*Tseq)   // 8192

// ---------------- scratch (no allocs allowed) ----------------
__device__ __align__(16) __half g_xf  [(size_t)Mrows * Cdim];
__device__ __align__(16) __half g_qkvh[(size_t)Mrows * C3];
__device__ __align__(16) __half g_qkvl[(size_t)Mrows * C3];
__device__ __align__(16) __half g_yf  [(size_t)Mrows * Cdim];
__device__ __align__(16) __half g_wqh [(size_t)C3 * Cdim];   // qkv_w^T  [N,K]
__device__ __align__(16) __half g_wql [(size_t)C3 * Cdim];
__device__ __align__(16) __half g_woh [(size_t)Cdim * Cdim]; // out_w^T  [N,K]
__device__ __align__(16) __half g_wol [(size_t)Cdim * Cdim];

// ================= portable PTX helpers =================
__device__ __forceinline__ uint32_t smem_u32(const void* p) {
    uint32_t a;
    asm("{ .reg .u64 t; cvta.to.shared.u64 t, %1; cvt.u32.u64 %0, t; }" : "=r"(a) : "l"(p));
    return a;
}
#define CP_ASYNC16(dst, src) \
    asm volatile("cp.async.cg.shared.global [%0], [%1], 16;" :: "r"(dst), "l"(src) : "memory")
#define CP_COMMIT() asm volatile("cp.async.commit_group;" ::: "memory")
#define CP_WAIT(n)  asm volatile("cp.async.wait_group %0;" :: "n"(n) : "memory")

__device__ __forceinline__ void ldsm_x4(uint32_t& r0, uint32_t& r1, uint32_t& r2, uint32_t& r3,
                                        uint32_t addr) {
    asm volatile("ldmatrix.sync.aligned.m8n8.x4.shared.b16 {%0,%1,%2,%3}, [%4];"
                 : "=r"(r0), "=r"(r1), "=r"(r2), "=r"(r3) : "r"(addr));
}
__device__ __forceinline__ void ldsm_x4_t(uint32_t& r0, uint32_t& r1, uint32_t& r2, uint32_t& r3,
                                          uint32_t addr) {
    asm volatile("ldmatrix.sync.aligned.m8n8.x4.trans.shared.b16 {%0,%1,%2,%3}, [%4];"
                 : "=r"(r0), "=r"(r1), "=r"(r2), "=r"(r3) : "r"(addr));
}
__device__ __forceinline__ void mma16816(float* d, const uint32_t* a, const uint32_t* b) {
    asm volatile(
        "mma.sync.aligned.m16n8k16.row.col.f32.f16.f16.f32 "
        "{%0,%1,%2,%3}, {%4,%5,%6,%7}, {%8,%9}, {%0,%1,%2,%3};"
        : "+f"(d[0]), "+f"(d[1]), "+f"(d[2]), "+f"(d[3])
        : "r"(a[0]), "r"(a[1]), "r"(a[2]), "r"(a[3]), "r"(b[0]), "r"(b[1]));
}
// pack two f32 -> f16x2 (lo half in bits [15:0])
__device__ __forceinline__ uint32_t packhf(float lo, float hi) {
    uint32_t d;
    asm("cvt.rn.f16x2.f32 %0, %1, %2;" : "=r"(d) : "f"(hi), "f"(lo));
    return d;
}
__device__ __forceinline__ float hflo(uint32_t u) {
    return __half2float(__ushort_as_half((unsigned short)(u & 0xffffu)));
}
__device__ __forceinline__ float hfhi(uint32_t u) {
    return __half2float(__ushort_as_half((unsigned short)(u >> 16)));
}

// ================= fp32 -> fp16 round (elementwise) =================
__global__ __launch_bounds__(256)
void round_kernel(const float* __restrict__ in, __half* __restrict__ outp, int n4)
{
    int i4 = blockIdx.x * blockDim.x + threadIdx.x;
    if (i4 >= n4) return;
    float4 v = ((const float4*)in)[i4];
    uint2 o;
    o.x = packhf(v.x, v.y);
    o.y = packhf(v.z, v.w);
    ((uint2*)outp)[i4] = o;
}

// ============ fp32 W[K,N] -> fp16 hi/lo transposed [N,K] ============
__global__ __launch_bounds__(256)
void splitT_kernel(const float* __restrict__ W, __half* __restrict__ Th,
                   __half* __restrict__ Tl, int K, int N)
{
    __shared__ float t[32][33];
    const int n0 = blockIdx.x * 32, k0 = blockIdx.y * 32;
    const int tx = threadIdx.x & 31, ty = (threadIdx.x >> 5);
    #pragma unroll
    for (int j = 0; j < 4; j++)
        t[ty + j*8][tx] = W[(size_t)(k0 + ty + j*8) * N + n0 + tx];
    __syncthreads();
    #pragma unroll
    for (int j = 0; j < 4; j++) {
        float v = t[tx][ty + j*8];
        __half h = __float2half_rn(v);
        __half l = __float2half_rn(v - __half2float(h));
        size_t oidx = (size_t)(n0 + ty + j*8) * K + k0 + tx;
        Th[oidx] = h;
        Tl[oidx] = l;
    }
}

// ================= warp-MMA 2-term fp16 GEMM =================
// C[M,N] = Af[M,K] @ (Bh+Bl)^T + bias, B given as [N,K] (K-major).
// block tile 128x128, K-step 32, 8 warps (4m x 2n), each warp 32x64.
// smem per stage: Af | Bh | Bl tiles (128 x 32 fp16, GPAD-padded rows).
#define GBM 128
#define GBN 128
#define GBK 32
#define GPAD 40
#define GTILE (128*GPAD*2)       // 10240 B
#define GSTAGE (3*GTILE)         // 30720 B
#define GEMM_SMEM (2*GSTAGE)     // 61440 B

template<bool SPLIT_OUT>
__global__ __launch_bounds__(256, 2)
void gemm_mma(const __half* __restrict__ Af,
              const __half* __restrict__ Bh, const __half* __restrict__ Bl,
              const float* __restrict__ bias, float* __restrict__ C,
              __half* __restrict__ Ch, __half* __restrict__ Cl,
              int M, int N, int K)
{
    extern __shared__ __align__(16) char gsm[];
    const uint32_t smBase = smem_u32(gsm);

    const int tid  = threadIdx.x;
    const int lane = tid & 31;
    const int wid  = tid >> 5;
    const int wm   = wid & 3;
    const int wn   = wid >> 2;
    const int rowBase = blockIdx.y * GBM;
    const int colBase = blockIdx.x * GBN;

    const int mat = lane >> 3, r8 = lane & 7;
    uint32_t aAddr[2], bAddr[4];
    #pragma unroll
    for (int mt = 0; mt < 2; mt++) {
        int row = wm * 32 + mt * 16 + (mat & 1) * 8 + r8;
        int col = (mat >> 1) * 8;
        aAddr[mt] = (uint32_t)(row * GPAD + col) * 2;
    }
    #pragma unroll
    for (int nt2 = 0; nt2 < 4; nt2++) {
        int row = wn * 64 + nt2 * 16 + (mat >> 1) * 8 + r8;
        int col = (mat & 1) * 8;
        bAddr[nt2] = (uint32_t)(row * GPAD + col) * 2;
    }

    float acc[2][8][4];
    #pragma unroll
    for (int i = 0; i < 2; i++)
        #pragma unroll
        for (int j = 0; j < 8; j++)
            #pragma unroll
            for (int q = 0; q < 4; q++) acc[i][j][q] = 0.f;

    const int KC = K / GBK;   // 24

    auto issue_tile = [&](int it) {
        const uint32_t stOff = (uint32_t)(it & 1) * GSTAGE;
        const int kc = it;
        #pragma unroll
        for (int i = 0; i < 6; i++) {              // 1536 chunks / 256 threads
            const int idx  = tid + i * 256;
            const int tile = idx >> 9;             // 0 Af, 1 Bh, 2 Bl
            const int r    = (idx & 511) >> 2;
            const int c8   = (idx & 3) * 8;
            const uint32_t dst = smBase + stOff + tile * GTILE
                               + (uint32_t)(r * GPAD + c8) * 2;
            const __half* src;
            if (tile == 0)      src = Af + (size_t)(rowBase + r) * K + kc * GBK + c8;
            else if (tile == 1) src = Bh + (size_t)(colBase + r) * K + kc * GBK + c8;
            else                src = Bl + (size_t)(colBase + r) * K + kc * GBK + c8;
            CP_ASYNC16(dst, src);
        }
        CP_COMMIT();
    };

    issue_tile(0);

    for (int it = 0; it < KC; ++it) {
        if (it + 1 < KC) { issue_tile(it + 1); CP_WAIT(1); }
        else             { CP_WAIT(0); }
        __syncthreads();

        const uint32_t stOff = smBase + (uint32_t)(it & 1) * GSTAGE;
        #pragma unroll
        for (int kk = 0; kk < 2; kk++) {
            uint32_t af[2][4], bf[8][2];
            #pragma unroll
            for (int mt = 0; mt < 2; mt++)
                ldsm_x4(af[mt][0], af[mt][1], af[mt][2], af[mt][3],
                        stOff + aAddr[mt] + kk * 32);
            // --- Bh term ---
            #pragma unroll
            for (int nt2 = 0; nt2 < 4; nt2++) {
                uint32_t r0, r1, r2, r3;
                ldsm_x4(r0, r1, r2, r3, stOff + GTILE + bAddr[nt2] + kk * 32);
                bf[nt2*2][0] = r0; bf[nt2*2][1] = r1;
                bf[nt2*2+1][0] = r2; bf[nt2*2+1][1] = r3;
            }
            #pragma unroll
            for (int mt = 0; mt < 2; mt++)
                #pragma unroll
                for (int nt = 0; nt < 8; nt++)
                    mma16816(acc[mt][nt], af[mt], bf[nt]);
            // --- Bl term ---
            #pragma unroll
            for (int nt2 = 0; nt2 < 4; nt2++) {
                uint32_t r0, r1, r2, r3;
                ldsm_x4(r0, r1, r2, r3, stOff + 2*GTILE + bAddr[nt2] + kk * 32);
                bf[nt2*2][0] = r0; bf[nt2*2][1] = r1;
                bf[nt2*2+1][0] = r2; bf[nt2*2+1][1] = r3;
            }
            #pragma unroll
            for (int mt = 0; mt < 2; mt++)
                #pragma unroll
                for (int nt = 0; nt < 8; nt++)
                    mma16816(acc[mt][nt], af[mt], bf[nt]);
        }
        __syncthreads();
    }

    const int g = lane >> 2, t = lane & 3;
    #pragma unroll
    for (int mt = 0; mt < 2; mt++) {
        #pragma unroll
        for (int nt = 0; nt < 8; nt++) {
            const int col = colBase + wn * 64 + nt * 8 + t * 2;
            const float b0 = bias[col], b1 = bias[col + 1];
            const int row0 = rowBase + wm * 32 + mt * 16 + g;
            float v0 = acc[mt][nt][0] + b0, v1 = acc[mt][nt][1] + b1;
            float v2 = acc[mt][nt][2] + b0, v3 = acc[mt][nt][3] + b1;
            if (SPLIT_OUT) {
                uint32_t h0 = packhf(v0, v1);
                uint32_t l0 = packhf(v0 - hflo(h0), v1 - hfhi(h0));
                uint32_t h1 = packhf(v2, v3);
                uint32_t l1 = packhf(v2 - hflo(h1), v3 - hfhi(h1));
                *(uint32_t*)(Ch + (size_t)row0 * N + col)       = h0;
                *(uint32_t*)(Cl + (size_t)row0 * N + col)       = l0;
                *(uint32_t*)(Ch + (size_t)(row0 + 8) * N + col) = h1;
                *(uint32_t*)(Cl + (size_t)(row0 + 8) * N + col) = l1;
            } else {
                *(float2*)&C[(size_t)row0 * N + col]       = make_float2(v0, v1);
                *(float2*)&C[(size_t)(row0 + 8) * N + col] = make_float2(v2, v3);
            }
        }
    }
}

// ================= tensor-core causal flash attention (fp16 2-term) =================
// CTA: 128 queries, 8 warps x 16 rows. K-tiles of 64. D = 64. 3-deep buffer ring.
#define PADK 72                       // fp16 per smem row (144B stride)
#define TILEB (64*PADK*2)             // 9216 B per 64x64 tile
#define BUFB  (4*TILEB)               // Kh,Kl,Vh,Vl = 36864 B per buffer
#define ATT_SMEM (3*BUFB)             // 110592 B (buffer2 doubles as Q staging)
#define ESC 0.18033688f               // 0.125 * log2(e)

__global__ __launch_bounds__(256)
void attn_mma(const __half* __restrict__ qkvh, const __half* __restrict__ qkvl,
              __half* __restrict__ yf)
{
    extern __shared__ __align__(16) char sm[];
    const uint32_t smBase = smem_u32(sm);

    const int tid  = threadIdx.x;
    const int lane = tid & 31;
    const int wm   = tid >> 5;
    const int bh = blockIdx.y;
    const int b  = bh / Hn;
    const int h  = bh % Hn;
    const int q0 = (gridDim.x - 1 - blockIdx.x) * 128;   // big tiles first

    const int mat = lane >> 3, r8 = lane & 7;
    const int g = lane >> 2, t = lane & 3;

    const int nk = q0 / 64 + 2;

    // ---- stage Qh into buffer2 region ----
    #pragma unroll
    for (int i = 0; i < 4; i++) {
        const int idx = tid + i * 256;          // 1024 chunks
        const int r   = idx >> 3;
        const int c8  = idx & 7;
        const uint32_t dst = smBase + 2u*BUFB + (uint32_t)(r * PADK + c8 * 8) * 2;
        const __half* src = qkvh + (size_t)(b * Tseq + q0 + r) * C3 + h * HD + c8 * 8;
        CP_ASYNC16(dst, src);
    }
    CP_COMMIT();

    // ldmatrix offsets within a K/V tile
    uint32_t kOff[4], vOff[4];
    #pragma unroll
    for (int nt2 = 0; nt2 < 4; nt2++) {
        kOff[nt2] = (uint32_t)((nt2 * 16 + (mat >> 1) * 8 + r8) * PADK + (mat & 1) * 8) * 2;
        vOff[nt2] = (uint32_t)(((mat & 1) * 8 + r8) * PADK + nt2 * 16 + (mat >> 1) * 8) * 2;
    }

    auto fill = [&](int it) {
        const int k0 = it * 64;
        const uint32_t bufOff = (uint32_t)(it % 3) * BUFB;
        #pragma unroll
        for (int i = 0; i < 8; i++) {
            const int idx = tid + i * 256;       // 2048 chunks
            const int tile = idx >> 9;           // 0 Kh, 1 Kl, 2 Vh, 3 Vl
            const int r    = (idx >> 3) & 63;
            const int c8   = idx & 7;
            const uint32_t dst = smBase + bufOff + tile * TILEB
                               + (uint32_t)(r * PADK + c8 * 8) * 2;
            const size_t srow = (size_t)(b * Tseq + k0 + r) * C3 + h * HD + c8 * 8
                              + ((tile >> 1) ? 2 * Cdim : Cdim);
            const __half* src = ((tile & 1) ? qkvl : qkvh) + srow;
            CP_ASYNC16(dst, src);
        }
        CP_COMMIT();
    };

    fill(0);
    fill(1);            // nk >= 2 always

    CP_WAIT(2);         // Q group (oldest) complete
    __syncthreads();

    uint32_t qh[4][4];
    {
        const uint32_t qrow = (uint32_t)(wm * 16 + (mat & 1) * 8 + r8);
        #pragma unroll
        for (int ks = 0; ks < 4; ks++) {
            const uint32_t off = (qrow * PADK + (uint32_t)(ks * 16 + (mat >> 1) * 8)) * 2;
            ldsm_x4(qh[ks][0], qh[ks][1], qh[ks][2], qh[ks][3], smBase + 2u*BUFB + off);
        }
    }
    __syncthreads();    // Q consumed; buffer2 reusable by fill(2)

    float O[8][4];
    #pragma unroll
    for (int nt = 0; nt < 8; nt++)
        #pragma unroll
        for (int q = 0; q < 4; q++) O[nt][q] = 0.f;
    float m0 = -1e30f, m1 = -1e30f, l0 = 0.f, l1 = 0.f;

    const int rowg0 = q0 + wm * 16 + g;
    const int rowg1 = rowg0 + 8;

    for (int it = 0; it < nk; ++it) {
        if (it + 2 < nk) fill(it + 2);
        {
            const int issued = (nk < it + 3) ? nk : (it + 3);
            const int rem = issued - (it + 1);
            if (rem >= 2)      { CP_WAIT(2); }
            else if (rem == 1) { CP_WAIT(1); }
            else               { CP_WAIT(0); }
        }
        __syncthreads();

        const int k0 = it * 64;
        const uint32_t bufO = smBase + (uint32_t)(it % 3) * BUFB;

        // ---- S = Qh·(Kh + Kl)^T ----
        float S[8][4];
        #pragma unroll
        for (int nt = 0; nt < 8; nt++)
            #pragma unroll
            for (int q = 0; q < 4; q++) S[nt][q] = 0.f;

        #pragma unroll
        for (int ks = 0; ks < 4; ks++) {
            uint32_t kf[8][2];
            #pragma unroll
            for (int nt2 = 0; nt2 < 4; nt2++) {
                uint32_t r0, r1, r2, r3;
                ldsm_x4(r0, r1, r2, r3, bufO + kOff[nt2] + ks * 32);
                kf[nt2*2][0] = r0; kf[nt2*2][1] = r1;
                kf[nt2*2+1][0] = r2; kf[nt2*2+1][1] = r3;
            }
            #pragma unroll
            for (int nt = 0; nt < 8; nt++) mma16816(S[nt], qh[ks], kf[nt]);
            #pragma unroll
            for (int nt2 = 0; nt2 < 4; nt2++) {
                uint32_t r0, r1, r2, r3;
                ldsm_x4(r0, r1, r2, r3, bufO + TILEB + kOff[nt2] + ks * 32);
                kf[nt2*2][0] = r0; kf[nt2*2][1] = r1;
                kf[nt2*2+1][0] = r2; kf[nt2*2+1][1] = r3;
            }
            #pragma unroll
            for (int nt = 0; nt < 8; nt++) mma16816(S[nt], qh[ks], kf[nt]);
        }

        // ---- causal mask (diagonal tiles only) ----
        if (k0 + 63 > q0 + wm * 16) {
            #pragma unroll
            for (int nt = 0; nt < 8; nt++) {
                const int c = k0 + nt * 8 + t * 2;
                if (c     > rowg0) S[nt][0] = -1e30f;
                if (c + 1 > rowg0) S[nt][1] = -1e30f;
                if (c     > rowg1) S[nt][2] = -1e30f;
                if (c + 1 > rowg1) S[nt][3] = -1e30f;
            }
        }

        // ---- online softmax ----
        float mx0 = -1e30f, mx1 = -1e30f;
        #pragma unroll
        for (int nt = 0; nt < 8; nt++) {
            mx0 = fmaxf(mx0, fmaxf(S[nt][0], S[nt][1]));
            mx1 = fmaxf(mx1, fmaxf(S[nt][2], S[nt][3]));
        }
        mx0 = fmaxf(mx0, __shfl_xor_sync(0xffffffffu, mx0, 1));
        mx0 = fmaxf(mx0, __shfl_xor_sync(0xffffffffu, mx0, 2));
        mx1 = fmaxf(mx1, __shfl_xor_sync(0xffffffffu, mx1, 1));
        mx1 = fmaxf(mx1, __shfl_xor_sync(0xffffffffu, mx1, 2));

        const float mn0 = fmaxf(m0, mx0);
        const float mn1 = fmaxf(m1, mx1);
        const float cr0 = exp2f((m0 - mn0) * ESC);
        const float cr1 = exp2f((m1 - mn1) * ESC);
        m0 = mn0; m1 = mn1;
        l0 *= cr0; l1 *= cr1;
        #pragma unroll
        for (int nt = 0; nt < 8; nt++) {
            O[nt][0] *= cr0; O[nt][1] *= cr0;
            O[nt][2] *= cr1; O[nt][3] *= cr1;
        }

        float rs0 = 0.f, rs1 = 0.f;
        #pragma unroll
        for (int nt = 0; nt < 8; nt++) {
            S[nt][0] = exp2f((S[nt][0] - mn0) * ESC);
            S[nt][1] = exp2f((S[nt][1] - mn0) * ESC);
            S[nt][2] = exp2f((S[nt][2] - mn1) * ESC);
            S[nt][3] = exp2f((S[nt][3] - mn1) * ESC);
            rs0 += S[nt][0] + S[nt][1];
            rs1 += S[nt][2] + S[nt][3];
        }
        rs0 += __shfl_xor_sync(0xffffffffu, rs0, 1);
        rs0 += __shfl_xor_sync(0xffffffffu, rs0, 2);
        rs1 += __shfl_xor_sync(0xffffffffu, rs1, 1);
        rs1 += __shfl_xor_sync(0xffffffffu, rs1, 2);
        l0 += rs0; l1 += rs1;

        // ---- P fp16 fragments (rounded; rounding is the budgeted error) ----
        uint32_t pf[4][4];
        #pragma unroll
        for (int kk = 0; kk < 4; kk++) {
            pf[kk][0] = packhf(S[2*kk][0],   S[2*kk][1]);
            pf[kk][1] = packhf(S[2*kk][2],   S[2*kk][3]);
            pf[kk][2] = packhf(S[2*kk+1][0], S[2*kk+1][1]);
            pf[kk][3] = packhf(S[2*kk+1][2], S[2*kk+1][3]);
        }

        // ---- O += Pf·(Vh + Vl) ----
        #pragma unroll
        for (int kk = 0; kk < 4; kk++) {
            uint32_t vf[8][2];
            #pragma unroll
            for (int nd2 = 0; nd2 < 4; nd2++) {
                uint32_t r0, r1, r2, r3;
                ldsm_x4_t(r0, r1, r2, r3, bufO + 2*TILEB + vOff[nd2] + kk * (PADK*16*2));
                vf[nd2*2][0] = r0; vf[nd2*2][1] = r1;
                vf[nd2*2+1][0] = r2; vf[nd2*2+1][1] = r3;
            }
            #pragma unroll
            for (int nd = 0; nd < 8; nd++) mma16816(O[nd], pf[kk], vf[nd]);
            #pragma unroll
            for (int nd2 = 0; nd2 < 4; nd2++) {
                uint32_t r0, r1, r2, r3;
                ldsm_x4_t(r0, r1, r2, r3, bufO + 3*TILEB + vOff[nd2] + kk * (PADK*16*2));
                vf[nd2*2][0] = r0; vf[nd2*2][1] = r1;
                vf[nd2*2+1][0] = r2; vf[nd2*2+1][1] = r3;
            }
            #pragma unroll
            for (int nd = 0; nd < 8; nd++) mma16816(O[nd], pf[kk], vf[nd]);
        }

        __syncthreads();   // buffer consumed; safe for future fill overwrite
    }

    // ---- epilogue: normalize, round to fp16, store ----
    const float i0 = 1.f / l0, i1 = 1.f / l1;
    const size_t base0 = (size_t)(b * Tseq + rowg0) * Cdim + h * HD;
    const size_t base1 = (size_t)(b * Tseq + rowg1) * Cdim + h * HD;
    #pragma unroll
    for (int nt = 0; nt < 8; nt++) {
        const int col = nt * 8 + t * 2;
        *(uint32_t*)(yf + base0 + col) = packhf(O[nt][0] * i0, O[nt][1] * i0);
        *(uint32_t*)(yf + base1 + col) = packhf(O[nt][2] * i1, O[nt][3] * i1);
    }
}

// ---------------- launch ----------------
extern "C" void kernel_launch(void* const* d_in, const int* in_sizes, int n_in,
                              void* d_out, int out_size)
{
    const float* x     = (const float*)d_in[0];
    const float* qkv_w = (const float*)d_in[1];
    const float* qkv_b = (const float*)d_in[2];
    const float* out_w = (const float*)d_in[3];
    const float* out_b = (const float*)d_in[4];
    float* out = (float*)d_out;

    __half *xf, *qh, *ql, *yf, *wqh, *wql, *woh, *wol;
    cudaGetSymbolAddress((void**)&xf, g_xf);
    cudaGetSymbolAddress((void**)&qh, g_qkvh);
    cudaGetSymbolAddress((void**)&ql, g_qkvl);
    cudaGetSymbolAddress((void**)&yf, g_yf);
    cudaGetSymbolAddress((void**)&wqh, g_wqh);
    cudaGetSymbolAddress((void**)&wql, g_wql);
    cudaGetSymbolAddress((void**)&woh, g_woh);
    cudaGetSymbolAddress((void**)&wol, g_wol);

    cudaFuncSetAttribute(gemm_mma<true>,  cudaFuncAttributeMaxDynamicSharedMemorySize, GEMM_SMEM);
    cudaFuncSetAttribute(gemm_mma<false>, cudaFuncAttributeMaxDynamicSharedMemorySize, GEMM_SMEM);
    cudaFuncSetAttribute(attn_mma, cudaFuncAttributeMaxDynamicSharedMemorySize, ATT_SMEM);

    const int M = Mrows;   // 8192

    {
        int n4 = (M * Cdim) / 4;
        round_kernel<<<(n4 + 255) / 256, 256>>>(x, xf, n4);
    }
    splitT_kernel<<<dim3(C3 / 32, Cdim / 32), 256>>>(qkv_w, wqh, wql, Cdim, C3);
    splitT_kernel<<<dim3(Cdim / 32, Cdim / 32), 256>>>(out_w, woh, wol, Cdim, Cdim);

    // 1) QKV projection -> fp16 hi/lo qkv
    gemm_mma<true><<<dim3(C3 / GBN, M / GBM), 256, GEMM_SMEM>>>(
        xf, wqh, wql, qkv_b, nullptr, qh, ql, M, C3, Cdim);

    // 2) causal attention -> fp16 y
    attn_mma<<<dim3(Tseq / 128, Bsz * Hn), 256, ATT_SMEM>>>(qh, ql, yf);

    // 3) output projection -> fp32 out
    gemm_mma<false><<<dim3(Cdim / GBN, M / GBM), 256, GEMM_SMEM>>>(
        yf, woh, wol, out_b, out, nullptr, nullptr, M, Cdim, Cdim);
}

// round 6
// speedup vs baseline: 6.0054x; 1.1129x over previous
#include <cuda_runtime.h>
#include <cuda_fp16.h>
#include <cstdint>
#include <math.h>

#define Bsz 2
#define Tseq 4096
#define Cdim 768
#define Hn 12
#define HD 64
#define C3 (3*Cdim)
#define Mrows (Bsz*Tseq)   // 8192

// ---------------- scratch (no allocs allowed) ----------------
__device__ __align__(16) __half g_xf  [(size_t)Mrows * Cdim];
__device__ __align__(16) __half g_qkvh[(size_t)Mrows * C3];
__device__ __align__(16) __half g_qkvl[(size_t)Mrows * C3];
__device__ __align__(16) __half g_yf  [(size_t)Mrows * Cdim];
__device__ __align__(16) __half g_wqh [(size_t)C3 * Cdim];   // qkv_w^T  [N,K]
__device__ __align__(16) __half g_wql [(size_t)C3 * Cdim];
__device__ __align__(16) __half g_woh [(size_t)Cdim * Cdim]; // out_w^T  [N,K]
__device__ __align__(16) __half g_wol [(size_t)Cdim * Cdim];

// ================= portable PTX helpers =================
__device__ __forceinline__ uint32_t smem_u32(const void* p) {
    uint32_t a;
    asm("{ .reg .u64 t; cvta.to.shared.u64 t, %1; cvt.u32.u64 %0, t; }" : "=r"(a) : "l"(p));
    return a;
}
#define CP_ASYNC16(dst, src) \
    asm volatile("cp.async.cg.shared.global [%0], [%1], 16;" :: "r"(dst), "l"(src) : "memory")
#define CP_COMMIT() asm volatile("cp.async.commit_group;" ::: "memory")
#define CP_WAIT(n)  asm volatile("cp.async.wait_group %0;" :: "n"(n) : "memory")

__device__ __forceinline__ void ldsm_x4(uint32_t& r0, uint32_t& r1, uint32_t& r2, uint32_t& r3,
                                        uint32_t addr) {
    asm volatile("ldmatrix.sync.aligned.m8n8.x4.shared.b16 {%0,%1,%2,%3}, [%4];"
                 : "=r"(r0), "=r"(r1), "=r"(r2), "=r"(r3) : "r"(addr));
}
__device__ __forceinline__ void ldsm_x4_t(uint32_t& r0, uint32_t& r1, uint32_t& r2, uint32_t& r3,
                                          uint32_t addr) {
    asm volatile("ldmatrix.sync.aligned.m8n8.x4.trans.shared.b16 {%0,%1,%2,%3}, [%4];"
                 : "=r"(r0), "=r"(r1), "=r"(r2), "=r"(r3) : "r"(addr));
}
__device__ __forceinline__ void mma16816(float* d, const uint32_t* a, const uint32_t* b) {
    asm volatile(
        "mma.sync.aligned.m16n8k16.row.col.f32.f16.f16.f32 "
        "{%0,%1,%2,%3}, {%4,%5,%6,%7}, {%8,%9}, {%0,%1,%2,%3};"
        : "+f"(d[0]), "+f"(d[1]), "+f"(d[2]), "+f"(d[3])
        : "r"(a[0]), "r"(a[1]), "r"(a[2]), "r"(a[3]), "r"(b[0]), "r"(b[1]));
}
__device__ __forceinline__ uint32_t packhf(float lo, float hi) {
    uint32_t d;
    asm("cvt.rn.f16x2.f32 %0, %1, %2;" : "=r"(d) : "f"(hi), "f"(lo));
    return d;
}
__device__ __forceinline__ float hflo(uint32_t u) {
    return __half2float(__ushort_as_half((unsigned short)(u & 0xffffu)));
}
__device__ __forceinline__ float hfhi(uint32_t u) {
    return __half2float(__ushort_as_half((unsigned short)(u >> 16)));
}

// ================= fp32 -> fp16 round (elementwise) =================
__global__ __launch_bounds__(256)
void round_kernel(const float* __restrict__ in, __half* __restrict__ outp, int n4)
{
    int i4 = blockIdx.x * blockDim.x + threadIdx.x;
    if (i4 >= n4) return;
    float4 v = ((const float4*)in)[i4];
    uint2 o;
    o.x = packhf(v.x, v.y);
    o.y = packhf(v.z, v.w);
    ((uint2*)outp)[i4] = o;
}

// ============ fp32 W[K,N] -> fp16 hi/lo transposed [N,K] ============
__global__ __launch_bounds__(256)
void splitT_kernel(const float* __restrict__ W, __half* __restrict__ Th,
                   __half* __restrict__ Tl, int K, int N)
{
    __shared__ float t[32][33];
    const int n0 = blockIdx.x * 32, k0 = blockIdx.y * 32;
    const int tx = threadIdx.x & 31, ty = (threadIdx.x >> 5);
    #pragma unroll
    for (int j = 0; j < 4; j++)
        t[ty + j*8][tx] = W[(size_t)(k0 + ty + j*8) * N + n0 + tx];
    __syncthreads();
    #pragma unroll
    for (int j = 0; j < 4; j++) {
        float v = t[tx][ty + j*8];
        __half h = __float2half_rn(v);
        __half l = __float2half_rn(v - __half2float(h));
        size_t oidx = (size_t)(n0 + ty + j*8) * K + k0 + tx;
        Th[oidx] = h;
        Tl[oidx] = l;
    }
}

// ================= warp-MMA 2-term fp16 GEMM (swizzled, K-step 64) =================
// C[M,N] = Af[M,K] @ (Bh+Bl)^T + bias, B given as [N,K] (K-major).
// block tile 128x128, 8 warps (4m x 2n), warp tile 32x64. 2-stage ring, 1 sync/iter.
#define GBM 128
#define GBN 128
#define GBK 64
#define GTILE 16384              // 128 rows x 128B (SW128)
#define GSTAGE (3*GTILE)         // Af | Bh | Bl = 49152 B
#define GEMM_SMEM (2*GSTAGE)     // 98304 B

template<bool SPLIT_OUT>
__global__ __launch_bounds__(256, 2)
void gemm_mma(const __half* __restrict__ Af,
              const __half* __restrict__ Bh, const __half* __restrict__ Bl,
              const float* __restrict__ bias, float* __restrict__ C,
              __half* __restrict__ Ch, __half* __restrict__ Cl,
              int M, int N, int K)
{
    extern __shared__ __align__(16) char gsm[];
    const uint32_t smBase = smem_u32(gsm);

    const int tid  = threadIdx.x;
    const int lane = tid & 31;
    const int wid  = tid >> 5;
    const int wm   = wid & 3;
    const int wn   = wid >> 2;
    const int rowBase = blockIdx.y * GBM;
    const int colBase = blockIdx.x * GBN;

    const int mat = lane >> 3, r8 = lane & 7;
    const uint32_t pat = (uint32_t)r8 << 4;     // swizzle pattern, lane-constant

    // fragment row bases (bytes) and swizzled column offsets per k16-step
    uint32_t aRow[2], bRow[4], acol[4], bcol[4];
    #pragma unroll
    for (int mt = 0; mt < 2; mt++)
        aRow[mt] = (uint32_t)(wm * 32 + mt * 16 + (mat & 1) * 8 + r8) * 128;
    #pragma unroll
    for (int nt2 = 0; nt2 < 4; nt2++)
        bRow[nt2] = (uint32_t)(wn * 64 + nt2 * 16 + (mat >> 1) * 8 + r8) * 128;
    #pragma unroll
    for (int kk = 0; kk < 4; kk++) {
        acol[kk] = (uint32_t)(kk * 32 + (mat >> 1) * 16) ^ pat;
        bcol[kk] = (uint32_t)(kk * 32 + (mat & 1) * 16) ^ pat;
    }

    float acc[2][8][4];
    #pragma unroll
    for (int i = 0; i < 2; i++)
        #pragma unroll
        for (int j = 0; j < 8; j++)
            #pragma unroll
            for (int q = 0; q < 4; q++) acc[i][j][q] = 0.f;

    const int KC = K / GBK;   // 12

    auto issue_tile = [&](int it) {
        const uint32_t stOff = (uint32_t)(it & 1) * GSTAGE;
        const int kc = it;
        #pragma unroll
        for (int i = 0; i < 12; i++) {             // 3072 chunks / 256 threads
            const int idx  = tid + i * 256;
            const int tile = idx >> 10;            // 0 Af, 1 Bh, 2 Bl
            const int rem  = idx & 1023;
            const int r    = rem >> 3;
            const int c8   = rem & 7;
            const uint32_t dst = smBase + stOff + (uint32_t)tile * GTILE
                               + (uint32_t)(r * 128 + ((c8 * 16) ^ ((r & 7) << 4)));
            const __half* src;
            if (tile == 0)      src = Af + (size_t)(rowBase + r) * K + kc * GBK + c8 * 8;
            else if (tile == 1) src = Bh + (size_t)(colBase + r) * K + kc * GBK + c8 * 8;
            else                src = Bl + (size_t)(colBase + r) * K + kc * GBK + c8 * 8;
            CP_ASYNC16(dst, src);
        }
        CP_COMMIT();
    };

    issue_tile(0);

    for (int it = 0; it < KC; ++it) {
        CP_WAIT(0);             // fill(it) complete (overlapped compute(it-1))
        __syncthreads();        // data visible; all warps finished compute(it-1)
        if (it + 1 < KC) issue_tile(it + 1);

        const uint32_t stOff = smBase + (uint32_t)(it & 1) * GSTAGE;
        #pragma unroll
        for (int kk = 0; kk < 4; kk++) {
            uint32_t af[2][4], bf[8][2];
            #pragma unroll
            for (int mt = 0; mt < 2; mt++)
                ldsm_x4(af[mt][0], af[mt][1], af[mt][2], af[mt][3],
                        stOff + aRow[mt] + acol[kk]);
            // --- Bh term ---
            #pragma unroll
            for (int nt2 = 0; nt2 < 4; nt2++) {
                uint32_t r0, r1, r2, r3;
                ldsm_x4(r0, r1, r2, r3, stOff + GTILE + bRow[nt2] + bcol[kk]);
                bf[nt2*2][0] = r0; bf[nt2*2][1] = r1;
                bf[nt2*2+1][0] = r2; bf[nt2*2+1][1] = r3;
            }
            #pragma unroll
            for (int mt = 0; mt < 2; mt++)
                #pragma unroll
                for (int nt = 0; nt < 8; nt++)
                    mma16816(acc[mt][nt], af[mt], bf[nt]);
            // --- Bl term ---
            #pragma unroll
            for (int nt2 = 0; nt2 < 4; nt2++) {
                uint32_t r0, r1, r2, r3;
                ldsm_x4(r0, r1, r2, r3, stOff + 2*GTILE + bRow[nt2] + bcol[kk]);
                bf[nt2*2][0] = r0; bf[nt2*2][1] = r1;
                bf[nt2*2+1][0] = r2; bf[nt2*2+1][1] = r3;
            }
            #pragma unroll
            for (int mt = 0; mt < 2; mt++)
                #pragma unroll
                for (int nt = 0; nt < 8; nt++)
                    mma16816(acc[mt][nt], af[mt], bf[nt]);
        }
    }

    const int g = lane >> 2, t = lane & 3;
    #pragma unroll
    for (int mt = 0; mt < 2; mt++) {
        #pragma unroll
        for (int nt = 0; nt < 8; nt++) {
            const int col = colBase + wn * 64 + nt * 8 + t * 2;
            const float b0 = bias[col], b1 = bias[col + 1];
            const int row0 = rowBase + wm * 32 + mt * 16 + g;
            float v0 = acc[mt][nt][0] + b0, v1 = acc[mt][nt][1] + b1;
            float v2 = acc[mt][nt][2] + b0, v3 = acc[mt][nt][3] + b1;
            if (SPLIT_OUT) {
                uint32_t h0 = packhf(v0, v1);
                uint32_t l0 = packhf(v0 - hflo(h0), v1 - hfhi(h0));
                uint32_t h1 = packhf(v2, v3);
                uint32_t l1 = packhf(v2 - hflo(h1), v3 - hfhi(h1));
                *(uint32_t*)(Ch + (size_t)row0 * N + col)       = h0;
                *(uint32_t*)(Cl + (size_t)row0 * N + col)       = l0;
                *(uint32_t*)(Ch + (size_t)(row0 + 8) * N + col) = h1;
                *(uint32_t*)(Cl + (size_t)(row0 + 8) * N + col) = l1;
            } else {
                *(float2*)&C[(size_t)row0 * N + col]       = make_float2(v0, v1);
                *(float2*)&C[(size_t)(row0 + 8) * N + col] = make_float2(v2, v3);
            }
        }
    }
}

// ================= tensor-core causal flash attention (fp16 2-term, swizzled) =================
// CTA: 128 queries, 8 warps x 16 rows. K-tiles of 64. D = 64. 3-stage ring, 1 sync/iter.
#define TILEB 8192                    // 64 rows x 128B (SW128)
#define BUFB  (4*TILEB)               // Kh,Kl,Vh,Vl = 32768 B
#define ATT_SMEM (3*BUFB)             // 98304 B (buffer2 doubles as Q staging)
#define ESC 0.18033688f               // 0.125 * log2(e)

__global__ __launch_bounds__(256, 2)
void attn_mma(const __half* __restrict__ qkvh, const __half* __restrict__ qkvl,
              __half* __restrict__ yf)
{
    extern __shared__ __align__(16) char sm[];
    const uint32_t smBase = smem_u32(sm);

    const int tid  = threadIdx.x;
    const int lane = tid & 31;
    const int wm   = tid >> 5;
    const int bh = blockIdx.y;
    const int b  = bh / Hn;
    const int h  = bh % Hn;
    const int q0 = (gridDim.x - 1 - blockIdx.x) * 128;   // big tiles first

    const int mat = lane >> 3, r8 = lane & 7;
    const int g = lane >> 2, t = lane & 3;
    const uint32_t pat = (uint32_t)r8 << 4;

    const int nk = q0 / 64 + 2;

    // ---- stage Qh into buffer2 region (swizzled 128B rows) ----
    #pragma unroll
    for (int i = 0; i < 4; i++) {
        const int idx = tid + i * 256;          // 1024 chunks
        const int r   = idx >> 3;
        const int c8  = idx & 7;
        const uint32_t dst = smBase + 2u*BUFB
                           + (uint32_t)(r * 128 + ((c8 * 16) ^ ((r & 7) << 4)));
        const __half* src = qkvh + (size_t)(b * Tseq + q0 + r) * C3 + h * HD + c8 * 8;
        CP_ASYNC16(dst, src);
    }
    CP_COMMIT();

    // fragment addressing (bytes)
    uint32_t kRow[4], kcol[4], qcol[4], vcol[4];
    #pragma unroll
    for (int nt2 = 0; nt2 < 4; nt2++) {
        kRow[nt2] = (uint32_t)(nt2 * 16 + (mat >> 1) * 8 + r8) * 128;
        vcol[nt2] = (uint32_t)(nt2 * 32 + (mat >> 1) * 16) ^ pat;
    }
    #pragma unroll
    for (int ks = 0; ks < 4; ks++) {
        kcol[ks] = (uint32_t)(ks * 32 + (mat & 1) * 16) ^ pat;
        qcol[ks] = (uint32_t)(ks * 32 + (mat >> 1) * 16) ^ pat;
    }
    const uint32_t qRow = (uint32_t)(wm * 16 + (mat & 1) * 8 + r8) * 128;
    const uint32_t vRow = (uint32_t)((mat & 1) * 8 + r8) * 128;

    auto fill = [&](int it) {
        const int k0 = it * 64;
        const uint32_t bufOff = (uint32_t)(it % 3) * BUFB;
        #pragma unroll
        for (int i = 0; i < 8; i++) {
            const int idx = tid + i * 256;       // 2048 chunks
            const int tile = idx >> 9;           // 0 Kh, 1 Kl, 2 Vh, 3 Vl
            const int r    = (idx >> 3) & 63;
            const int c8   = idx & 7;
            const uint32_t dst = smBase + bufOff + (uint32_t)tile * TILEB
                               + (uint32_t)(r * 128 + ((c8 * 16) ^ ((r & 7) << 4)));
            const size_t srow = (size_t)(b * Tseq + k0 + r) * C3 + h * HD + c8 * 8
                              + ((tile >> 1) ? 2 * Cdim : Cdim);
            const __half* src = ((tile & 1) ? qkvl : qkvh) + srow;
            CP_ASYNC16(dst, src);
        }
        CP_COMMIT();
    };

    fill(0);
    fill(1);            // nk >= 2 always

    CP_WAIT(2);         // Q group (oldest) complete
    __syncthreads();

    uint32_t qh[4][4];
    #pragma unroll
    for (int ks = 0; ks < 4; ks++)
        ldsm_x4(qh[ks][0], qh[ks][1], qh[ks][2], qh[ks][3],
                smBase + 2u*BUFB + qRow + qcol[ks]);
    // no sync needed here: iter-0 sync below precedes any overwrite of buffer2

    float O[8][4];
    #pragma unroll
    for (int nt = 0; nt < 8; nt++)
        #pragma unroll
        for (int q = 0; q < 4; q++) O[nt][q] = 0.f;
    float m0 = -1e30f, m1 = -1e30f, l0 = 0.f, l1 = 0.f;

    const int rowg0 = q0 + wm * 16 + g;
    const int rowg1 = rowg0 + 8;

    for (int it = 0; it < nk; ++it) {
        if (it < nk - 1) { CP_WAIT(1); } else { CP_WAIT(0); }
        __syncthreads();                        // fill(it) visible; compute(it-1) done everywhere
        if (it + 2 < nk) fill(it + 2);          // overwrites buffer consumed at it-1: safe

        const int k0 = it * 64;
        const uint32_t bufO = smBase + (uint32_t)(it % 3) * BUFB;

        // ---- S = Qh·(Kh + Kl)^T ----
        float S[8][4];
        #pragma unroll
        for (int nt = 0; nt < 8; nt++)
            #pragma unroll
            for (int q = 0; q < 4; q++) S[nt][q] = 0.f;

        #pragma unroll
        for (int ks = 0; ks < 4; ks++) {
            uint32_t kf[8][2];
            #pragma unroll
            for (int nt2 = 0; nt2 < 4; nt2++) {
                uint32_t r0, r1, r2, r3;
                ldsm_x4(r0, r1, r2, r3, bufO + kRow[nt2] + kcol[ks]);
                kf[nt2*2][0] = r0; kf[nt2*2][1] = r1;
                kf[nt2*2+1][0] = r2; kf[nt2*2+1][1] = r3;
            }
            #pragma unroll
            for (int nt = 0; nt < 8; nt++) mma16816(S[nt], qh[ks], kf[nt]);
            #pragma unroll
            for (int nt2 = 0; nt2 < 4; nt2++) {
                uint32_t r0, r1, r2, r3;
                ldsm_x4(r0, r1, r2, r3, bufO + TILEB + kRow[nt2] + kcol[ks]);
                kf[nt2*2][0] = r0; kf[nt2*2][1] = r1;
                kf[nt2*2+1][0] = r2; kf[nt2*2+1][1] = r3;
            }
            #pragma unroll
            for (int nt = 0; nt < 8; nt++) mma16816(S[nt], qh[ks], kf[nt]);
        }

        // ---- causal mask (diagonal tiles only) ----
        if (k0 + 63 > q0 + wm * 16) {
            #pragma unroll
            for (int nt = 0; nt < 8; nt++) {
                const int c = k0 + nt * 8 + t * 2;
                if (c     > rowg0) S[nt][0] = -1e30f;
                if (c + 1 > rowg0) S[nt][1] = -1e30f;
                if (c     > rowg1) S[nt][2] = -1e30f;
                if (c + 1 > rowg1) S[nt][3] = -1e30f;
            }
        }

        // ---- online softmax ----
        float mx0 = -1e30f, mx1 = -1e30f;
        #pragma unroll
        for (int nt = 0; nt < 8; nt++) {
            mx0 = fmaxf(mx0, fmaxf(S[nt][0], S[nt][1]));
            mx1 = fmaxf(mx1, fmaxf(S[nt][2], S[nt][3]));
        }
        mx0 = fmaxf(mx0, __shfl_xor_sync(0xffffffffu, mx0, 1));
        mx0 = fmaxf(mx0, __shfl_xor_sync(0xffffffffu, mx0, 2));
        mx1 = fmaxf(mx1, __shfl_xor_sync(0xffffffffu, mx1, 1));
        mx1 = fmaxf(mx1, __shfl_xor_sync(0xffffffffu, mx1, 2));

        const float mn0 = fmaxf(m0, mx0);
        const float mn1 = fmaxf(m1, mx1);
        const float cr0 = exp2f((m0 - mn0) * ESC);
        const float cr1 = exp2f((m1 - mn1) * ESC);
        m0 = mn0; m1 = mn1;
        l0 *= cr0; l1 *= cr1;
        #pragma unroll
        for (int nt = 0; nt < 8; nt++) {
            O[nt][0] *= cr0; O[nt][1] *= cr0;
            O[nt][2] *= cr1; O[nt][3] *= cr1;
        }

        float rs0 = 0.f, rs1 = 0.f;
        #pragma unroll
        for (int nt = 0; nt < 8; nt++) {
            S[nt][0] = exp2f((S[nt][0] - mn0) * ESC);
            S[nt][1] = exp2f((S[nt][1] - mn0) * ESC);
            S[nt][2] = exp2f((S[nt][2] - mn1) * ESC);
            S[nt][3] = exp2f((S[nt][3] - mn1) * ESC);
            rs0 += S[nt][0] + S[nt][1];
            rs1 += S[nt][2] + S[nt][3];
        }
        rs0 += __shfl_xor_sync(0xffffffffu, rs0, 1);
        rs0 += __shfl_xor_sync(0xffffffffu, rs0, 2);
        rs1 += __shfl_xor_sync(0xffffffffu, rs1, 1);
        rs1 += __shfl_xor_sync(0xffffffffu, rs1, 2);
        l0 += rs0; l1 += rs1;

        // ---- P fp16 fragments ----
        uint32_t pf[4][4];
        #pragma unroll
        for (int kk = 0; kk < 4; kk++) {
            pf[kk][0] = packhf(S[2*kk][0],   S[2*kk][1]);
            pf[kk][1] = packhf(S[2*kk][2],   S[2*kk][3]);
            pf[kk][2] = packhf(S[2*kk+1][0], S[2*kk+1][1]);
            pf[kk][3] = packhf(S[2*kk+1][2], S[2*kk+1][3]);
        }

        // ---- O += Pf·(Vh + Vl) ----
        #pragma unroll
        for (int kk = 0; kk < 4; kk++) {
            uint32_t vf[8][2];
            #pragma unroll
            for (int nd2 = 0; nd2 < 4; nd2++) {
                uint32_t r0, r1, r2, r3;
                ldsm_x4_t(r0, r1, r2, r3, bufO + 2*TILEB + vRow + kk * 2048 + vcol[nd2]);
                vf[nd2*2][0] = r0; vf[nd2*2][1] = r1;
                vf[nd2*2+1][0] = r2; vf[nd2*2+1][1] = r3;
            }
            #pragma unroll
            for (int nd = 0; nd < 8; nd++) mma16816(O[nd], pf[kk], vf[nd]);
            #pragma unroll
            for (int nd2 = 0; nd2 < 4; nd2++) {
                uint32_t r0, r1, r2, r3;
                ldsm_x4_t(r0, r1, r2, r3, bufO + 3*TILEB + vRow + kk * 2048 + vcol[nd2]);
                vf[nd2*2][0] = r0; vf[nd2*2][1] = r1;
                vf[nd2*2+1][0] = r2; vf[nd2*2+1][1] = r3;
            }
            #pragma unroll
            for (int nd = 0; nd < 8; nd++) mma16816(O[nd], pf[kk], vf[nd]);
        }
    }

    // ---- epilogue: normalize, round to fp16, store ----
    const float i0 = 1.f / l0, i1 = 1.f / l1;
    const size_t base0 = (size_t)(b * Tseq + rowg0) * Cdim + h * HD;
    const size_t base1 = (size_t)(b * Tseq + rowg1) * Cdim + h * HD;
    #pragma unroll
    for (int nt = 0; nt < 8; nt++) {
        const int col = nt * 8 + t * 2;
        *(uint32_t*)(yf + base0 + col) = packhf(O[nt][0] * i0, O[nt][1] * i0);
        *(uint32_t*)(yf + base1 + col) = packhf(O[nt][2] * i1, O[nt][3] * i1);
    }
}

// ---------------- launch ----------------
extern "C" void kernel_launch(void* const* d_in, const int* in_sizes, int n_in,
                              void* d_out, int out_size)
{
    const float* x     = (const float*)d_in[0];
    const float* qkv_w = (const float*)d_in[1];
    const float* qkv_b = (const float*)d_in[2];
    const float* out_w = (const float*)d_in[3];
    const float* out_b = (const float*)d_in[4];
    float* out = (float*)d_out;

    __half *xf, *qh, *ql, *yf, *wqh, *wql, *woh, *wol;
    cudaGetSymbolAddress((void**)&xf, g_xf);
    cudaGetSymbolAddress((void**)&qh, g_qkvh);
    cudaGetSymbolAddress((void**)&ql, g_qkvl);
    cudaGetSymbolAddress((void**)&yf, g_yf);
    cudaGetSymbolAddress((void**)&wqh, g_wqh);
    cudaGetSymbolAddress((void**)&wql, g_wql);
    cudaGetSymbolAddress((void**)&woh, g_woh);
    cudaGetSymbolAddress((void**)&wol, g_wol);

    cudaFuncSetAttribute(gemm_mma<true>,  cudaFuncAttributeMaxDynamicSharedMemorySize, GEMM_SMEM);
    cudaFuncSetAttribute(gemm_mma<false>, cudaFuncAttributeMaxDynamicSharedMemorySize, GEMM_SMEM);
    cudaFuncSetAttribute(attn_mma, cudaFuncAttributeMaxDynamicSharedMemorySize, ATT_SMEM);

    const int M = Mrows;   // 8192

    {
        int n4 = (M * Cdim) / 4;
        round_kernel<<<(n4 + 255) / 256, 256>>>(x, xf, n4);
    }
    splitT_kernel<<<dim3(C3 / 32, Cdim / 32), 256>>>(qkv_w, wqh, wql, Cdim, C3);
    splitT_kernel<<<dim3(Cdim / 32, Cdim / 32), 256>>>(out_w, woh, wol, Cdim, Cdim);

    // 1) QKV projection -> fp16 hi/lo qkv
    gemm_mma<true><<<dim3(C3 / GBN, M / GBM), 256, GEMM_SMEM>>>(
        xf, wqh, wql, qkv_b, nullptr, qh, ql, M, C3, Cdim);

    // 2) causal attention -> fp16 y
    attn_mma<<<dim3(Tseq / 128, Bsz * Hn), 256, ATT_SMEM>>>(qh, ql, yf);

    // 3) output projection -> fp32 out
    gemm_mma<false><<<dim3(Cdim / GBN, M / GBM), 256, GEMM_SMEM>>>(
        yf, woh, wol, out_b, out, nullptr, nullptr, M, Cdim, Cdim);
}

// round 7
// speedup vs baseline: 8.1188x; 1.3519x over previous
#include <cuda_runtime.h>
#include <cuda_fp16.h>
#include <cstdint>
#include <math.h>

#define Bsz 2
#define Tseq 4096
#define Cdim 768
#define Hn 12
#define HD 64
#define C3 (3*Cdim)
#define Mrows (Bsz*Tseq)   // 8192

// ---------------- scratch (no allocs allowed) ----------------
__device__ __align__(16) __half g_xf  [(size_t)Mrows * Cdim];
__device__ __align__(16) __half g_qkvf[(size_t)Mrows * C3];
__device__ __align__(16) __half g_yf  [(size_t)Mrows * Cdim];
__device__ __align__(16) __half g_wqh [(size_t)C3 * Cdim];   // qkv_w^T  [N,K]
__device__ __align__(16) __half g_wql [(size_t)C3 * Cdim];
__device__ __align__(16) __half g_woh [(size_t)Cdim * Cdim]; // out_w^T  [N,K]
__device__ __align__(16) __half g_wol [(size_t)Cdim * Cdim];

// ================= portable PTX helpers =================
__device__ __forceinline__ uint32_t smem_u32(const void* p) {
    uint32_t a;
    asm("{ .reg .u64 t; cvta.to.shared.u64 t, %1; cvt.u32.u64 %0, t; }" : "=r"(a) : "l"(p));
    return a;
}
#define CP_ASYNC16(dst, src) \
    asm volatile("cp.async.cg.shared.global [%0], [%1], 16;" :: "r"(dst), "l"(src) : "memory")
#define CP_COMMIT() asm volatile("cp.async.commit_group;" ::: "memory")
#define CP_WAIT(n)  asm volatile("cp.async.wait_group %0;" :: "n"(n) : "memory")

__device__ __forceinline__ void ldsm_x4(uint32_t& r0, uint32_t& r1, uint32_t& r2, uint32_t& r3,
                                        uint32_t addr) {
    asm volatile("ldmatrix.sync.aligned.m8n8.x4.shared.b16 {%0,%1,%2,%3}, [%4];"
                 : "=r"(r0), "=r"(r1), "=r"(r2), "=r"(r3) : "r"(addr));
}
__device__ __forceinline__ void ldsm_x4_t(uint32_t& r0, uint32_t& r1, uint32_t& r2, uint32_t& r3,
                                          uint32_t addr) {
    asm volatile("ldmatrix.sync.aligned.m8n8.x4.trans.shared.b16 {%0,%1,%2,%3}, [%4];"
                 : "=r"(r0), "=r"(r1), "=r"(r2), "=r"(r3) : "r"(addr));
}
__device__ __forceinline__ void mma16816(float* d, const uint32_t* a, const uint32_t* b) {
    asm volatile(
        "mma.sync.aligned.m16n8k16.row.col.f32.f16.f16.f32 "
        "{%0,%1,%2,%3}, {%4,%5,%6,%7}, {%8,%9}, {%0,%1,%2,%3};"
        : "+f"(d[0]), "+f"(d[1]), "+f"(d[2]), "+f"(d[3])
        : "r"(a[0]), "r"(a[1]), "r"(a[2]), "r"(a[3]), "r"(b[0]), "r"(b[1]));
}
__device__ __forceinline__ uint32_t packhf(float lo, float hi) {
    uint32_t d;
    asm("cvt.rn.f16x2.f32 %0, %1, %2;" : "=r"(d) : "f"(hi), "f"(lo));
    return d;
}

// ================= fp32 -> fp16 round (elementwise) =================
__global__ __launch_bounds__(256)
void round_kernel(const float* __restrict__ in, __half* __restrict__ outp, int n4)
{
    int i4 = blockIdx.x * blockDim.x + threadIdx.x;
    if (i4 >= n4) return;
    float4 v = ((const float4*)in)[i4];
    uint2 o;
    o.x = packhf(v.x, v.y);
    o.y = packhf(v.z, v.w);
    ((uint2*)outp)[i4] = o;
}

// ============ fp32 W[K,N] -> fp16 hi/lo transposed [N,K] ============
__global__ __launch_bounds__(256)
void splitT_kernel(const float* __restrict__ W, __half* __restrict__ Th,
                   __half* __restrict__ Tl, int K, int N)
{
    __shared__ float t[32][33];
    const int n0 = blockIdx.x * 32, k0 = blockIdx.y * 32;
    const int tx = threadIdx.x & 31, ty = (threadIdx.x >> 5);
    #pragma unroll
    for (int j = 0; j < 4; j++)
        t[ty + j*8][tx] = W[(size_t)(k0 + ty + j*8) * N + n0 + tx];
    __syncthreads();
    #pragma unroll
    for (int j = 0; j < 4; j++) {
        float v = t[tx][ty + j*8];
        __half h = __float2half_rn(v);
        __half l = __float2half_rn(v - __half2float(h));
        size_t oidx = (size_t)(n0 + ty + j*8) * K + k0 + tx;
        Th[oidx] = h;
        Tl[oidx] = l;
    }
}

// ================= warp-MMA 2-term fp16 GEMM (swizzled, K-step 64) =================
// C[M,N] = Af[M,K] @ (Bh+Bl)^T + bias, B given as [N,K] (K-major).
// block tile 128x128, 8 warps (4m x 2n), warp tile 32x64. 2-stage ring, 1 sync/iter.
#define GBM 128
#define GBN 128
#define GBK 64
#define GTILE 16384              // 128 rows x 128B (SW128)
#define GSTAGE (3*GTILE)         // Af | Bh | Bl = 49152 B
#define GEMM_SMEM (2*GSTAGE)     // 98304 B

template<bool F16OUT>
__global__ __launch_bounds__(256, 2)
void gemm_mma(const __half* __restrict__ Af,
              const __half* __restrict__ Bh, const __half* __restrict__ Bl,
              const float* __restrict__ bias, float* __restrict__ C,
              __half* __restrict__ Cf,
              int M, int N, int K)
{
    extern __shared__ __align__(16) char gsm[];
    const uint32_t smBase = smem_u32(gsm);

    const int tid  = threadIdx.x;
    const int lane = tid & 31;
    const int wid  = tid >> 5;
    const int wm   = wid & 3;
    const int wn   = wid >> 2;
    const int rowBase = blockIdx.y * GBM;
    const int colBase = blockIdx.x * GBN;

    const int mat = lane >> 3, r8 = lane & 7;
    const uint32_t pat = (uint32_t)r8 << 4;     // swizzle pattern, lane-constant

    uint32_t aRow[2], bRow[4], acol[4], bcol[4];
    #pragma unroll
    for (int mt = 0; mt < 2; mt++)
        aRow[mt] = (uint32_t)(wm * 32 + mt * 16 + (mat & 1) * 8 + r8) * 128;
    #pragma unroll
    for (int nt2 = 0; nt2 < 4; nt2++)
        bRow[nt2] = (uint32_t)(wn * 64 + nt2 * 16 + (mat >> 1) * 8 + r8) * 128;
    #pragma unroll
    for (int kk = 0; kk < 4; kk++) {
        acol[kk] = (uint32_t)(kk * 32 + (mat >> 1) * 16) ^ pat;
        bcol[kk] = (uint32_t)(kk * 32 + (mat & 1) * 16) ^ pat;
    }

    float acc[2][8][4];
    #pragma unroll
    for (int i = 0; i < 2; i++)
        #pragma unroll
        for (int j = 0; j < 8; j++)
            #pragma unroll
            for (int q = 0; q < 4; q++) acc[i][j][q] = 0.f;

    const int KC = K / GBK;   // 12

    auto issue_tile = [&](int it) {
        const uint32_t stOff = (uint32_t)(it & 1) * GSTAGE;
        const int kc = it;
        #pragma unroll
        for (int i = 0; i < 12; i++) {             // 3072 chunks / 256 threads
            const int idx  = tid + i * 256;
            const int tile = idx >> 10;            // 0 Af, 1 Bh, 2 Bl
            const int rem  = idx & 1023;
            const int r    = rem >> 3;
            const int c8   = rem & 7;
            const uint32_t dst = smBase + stOff + (uint32_t)tile * GTILE
                               + (uint32_t)(r * 128 + ((c8 * 16) ^ ((r & 7) << 4)));
            const __half* src;
            if (tile == 0)      src = Af + (size_t)(rowBase + r) * K + kc * GBK + c8 * 8;
            else if (tile == 1) src = Bh + (size_t)(colBase + r) * K + kc * GBK + c8 * 8;
            else                src = Bl + (size_t)(colBase + r) * K + kc * GBK + c8 * 8;
            CP_ASYNC16(dst, src);
        }
        CP_COMMIT();
    };

    issue_tile(0);

    for (int it = 0; it < KC; ++it) {
        CP_WAIT(0);
        __syncthreads();
        if (it + 1 < KC) issue_tile(it + 1);

        const uint32_t stOff = smBase + (uint32_t)(it & 1) * GSTAGE;
        #pragma unroll
        for (int kk = 0; kk < 4; kk++) {
            uint32_t af[2][4], bf[8][2];
            #pragma unroll
            for (int mt = 0; mt < 2; mt++)
                ldsm_x4(af[mt][0], af[mt][1], af[mt][2], af[mt][3],
                        stOff + aRow[mt] + acol[kk]);
            // --- Bh term ---
            #pragma unroll
            for (int nt2 = 0; nt2 < 4; nt2++) {
                uint32_t r0, r1, r2, r3;
                ldsm_x4(r0, r1, r2, r3, stOff + GTILE + bRow[nt2] + bcol[kk]);
                bf[nt2*2][0] = r0; bf[nt2*2][1] = r1;
                bf[nt2*2+1][0] = r2; bf[nt2*2+1][1] = r3;
            }
            #pragma unroll
            for (int mt = 0; mt < 2; mt++)
                #pragma unroll
                for (int nt = 0; nt < 8; nt++)
                    mma16816(acc[mt][nt], af[mt], bf[nt]);
            // --- Bl term ---
            #pragma unroll
            for (int nt2 = 0; nt2 < 4; nt2++) {
                uint32_t r0, r1, r2, r3;
                ldsm_x4(r0, r1, r2, r3, stOff + 2*GTILE + bRow[nt2] + bcol[kk]);
                bf[nt2*2][0] = r0; bf[nt2*2][1] = r1;
                bf[nt2*2+1][0] = r2; bf[nt2*2+1][1] = r3;
            }
            #pragma unroll
            for (int mt = 0; mt < 2; mt++)
                #pragma unroll
                for (int nt = 0; nt < 8; nt++)
                    mma16816(acc[mt][nt], af[mt], bf[nt]);
        }
    }

    const int g = lane >> 2, t = lane & 3;
    #pragma unroll
    for (int mt = 0; mt < 2; mt++) {
        #pragma unroll
        for (int nt = 0; nt < 8; nt++) {
            const int col = colBase + wn * 64 + nt * 8 + t * 2;
            const float b0 = bias[col], b1 = bias[col + 1];
            const int row0 = rowBase + wm * 32 + mt * 16 + g;
            float v0 = acc[mt][nt][0] + b0, v1 = acc[mt][nt][1] + b1;
            float v2 = acc[mt][nt][2] + b0, v3 = acc[mt][nt][3] + b1;
            if (F16OUT) {
                *(uint32_t*)(Cf + (size_t)row0 * N + col)       = packhf(v0, v1);
                *(uint32_t*)(Cf + (size_t)(row0 + 8) * N + col) = packhf(v2, v3);
            } else {
                *(float2*)&C[(size_t)row0 * N + col]       = make_float2(v0, v1);
                *(float2*)&C[(size_t)(row0 + 8) * N + col] = make_float2(v2, v3);
            }
        }
    }
}

// ================= tensor-core causal flash attention (fp16, swizzled) =================
// CTA: 128 queries, 8 warps x 16 rows. K-tiles of 64. D = 64. 3-stage ring, 1 sync/iter.
#define TILEB 8192                    // 64 rows x 128B (SW128)
#define BUFB  (2*TILEB)               // K, V = 16384 B
#define ATT_SMEM (3*BUFB)             // 49152 B (buffer2 doubles as Q staging: 16 KB)
#define ESC 0.18033688f               // 0.125 * log2(e)

__global__ __launch_bounds__(256, 2)
void attn_mma(const __half* __restrict__ qkv, __half* __restrict__ yf)
{
    extern __shared__ __align__(16) char sm[];
    const uint32_t smBase = smem_u32(sm);

    const int tid  = threadIdx.x;
    const int lane = tid & 31;
    const int wm   = tid >> 5;
    const int bh = blockIdx.y;
    const int b  = bh / Hn;
    const int h  = bh % Hn;
    const int q0 = (gridDim.x - 1 - blockIdx.x) * 128;   // big tiles first

    const int mat = lane >> 3, r8 = lane & 7;
    const int g = lane >> 2, t = lane & 3;
    const uint32_t pat = (uint32_t)r8 << 4;

    const int nk = q0 / 64 + 2;

    // ---- stage Q into buffer2 region (swizzled 128B rows, 16 KB) ----
    #pragma unroll
    for (int i = 0; i < 4; i++) {
        const int idx = tid + i * 256;          // 1024 chunks
        const int r   = idx >> 3;
        const int c8  = idx & 7;
        const uint32_t dst = smBase + 2u*BUFB
                           + (uint32_t)(r * 128 + ((c8 * 16) ^ ((r & 7) << 4)));
        const __half* src = qkv + (size_t)(b * Tseq + q0 + r) * C3 + h * HD + c8 * 8;
        CP_ASYNC16(dst, src);
    }
    CP_COMMIT();

    // fragment addressing (bytes)
    uint32_t kRow[4], kcol[4], qcol[4], vcol[4];
    #pragma unroll
    for (int nt2 = 0; nt2 < 4; nt2++) {
        kRow[nt2] = (uint32_t)(nt2 * 16 + (mat >> 1) * 8 + r8) * 128;
        vcol[nt2] = (uint32_t)(nt2 * 32 + (mat >> 1) * 16) ^ pat;
    }
    #pragma unroll
    for (int ks = 0; ks < 4; ks++) {
        kcol[ks] = (uint32_t)(ks * 32 + (mat & 1) * 16) ^ pat;
        qcol[ks] = (uint32_t)(ks * 32 + (mat >> 1) * 16) ^ pat;
    }
    const uint32_t qRow = (uint32_t)(wm * 16 + (mat & 1) * 8 + r8) * 128;
    const uint32_t vRow = (uint32_t)((mat & 1) * 8 + r8) * 128;

    auto fill = [&](int it) {
        const int k0 = it * 64;
        const uint32_t bufOff = (uint32_t)(it % 3) * BUFB;
        #pragma unroll
        for (int i = 0; i < 4; i++) {
            const int idx = tid + i * 256;       // 1024 chunks
            const int tile = idx >> 9;           // 0 K, 1 V
            const int r    = (idx >> 3) & 63;
            const int c8   = idx & 7;
            const uint32_t dst = smBase + bufOff + (uint32_t)tile * TILEB
                               + (uint32_t)(r * 128 + ((c8 * 16) ^ ((r & 7) << 4)));
            const __half* src = qkv + (size_t)(b * Tseq + k0 + r) * C3 + h * HD + c8 * 8
                              + (tile ? 2 * Cdim : Cdim);
            CP_ASYNC16(dst, src);
        }
        CP_COMMIT();
    };

    fill(0);
    fill(1);            // nk >= 2 always

    CP_WAIT(2);         // Q group (oldest) complete
    __syncthreads();

    uint32_t qf[4][4];
    #pragma unroll
    for (int ks = 0; ks < 4; ks++)
        ldsm_x4(qf[ks][0], qf[ks][1], qf[ks][2], qf[ks][3],
                smBase + 2u*BUFB + qRow + qcol[ks]);
    // iter-0 sync below precedes any overwrite of buffer2

    float O[8][4];
    #pragma unroll
    for (int nt = 0; nt < 8; nt++)
        #pragma unroll
        for (int q = 0; q < 4; q++) O[nt][q] = 0.f;
    float m0 = -1e30f, m1 = -1e30f, l0 = 0.f, l1 = 0.f;

    const int rowg0 = q0 + wm * 16 + g;
    const int rowg1 = rowg0 + 8;

    for (int it = 0; it < nk; ++it) {
        if (it < nk - 1) { CP_WAIT(1); } else { CP_WAIT(0); }
        __syncthreads();
        if (it + 2 < nk) fill(it + 2);

        const int k0 = it * 64;
        const uint32_t bufO = smBase + (uint32_t)(it % 3) * BUFB;

        // ---- S = Qf·Kf^T ----
        float S[8][4];
        #pragma unroll
        for (int nt = 0; nt < 8; nt++)
            #pragma unroll
            for (int q = 0; q < 4; q++) S[nt][q] = 0.f;

        #pragma unroll
        for (int ks = 0; ks < 4; ks++) {
            uint32_t kf[8][2];
            #pragma unroll
            for (int nt2 = 0; nt2 < 4; nt2++) {
                uint32_t r0, r1, r2, r3;
                ldsm_x4(r0, r1, r2, r3, bufO + kRow[nt2] + kcol[ks]);
                kf[nt2*2][0] = r0; kf[nt2*2][1] = r1;
                kf[nt2*2+1][0] = r2; kf[nt2*2+1][1] = r3;
            }
            #pragma unroll
            for (int nt = 0; nt < 8; nt++) mma16816(S[nt], qf[ks], kf[nt]);
        }

        // ---- causal mask (diagonal tiles only) ----
        if (k0 + 63 > q0 + wm * 16) {
            #pragma unroll
            for (int nt = 0; nt < 8; nt++) {
                const int c = k0 + nt * 8 + t * 2;
                if (c     > rowg0) S[nt][0] = -1e30f;
                if (c + 1 > rowg0) S[nt][1] = -1e30f;
                if (c     > rowg1) S[nt][2] = -1e30f;
                if (c + 1 > rowg1) S[nt][3] = -1e30f;
            }
        }

        // ---- online softmax ----
        float mx0 = -1e30f, mx1 = -1e30f;
        #pragma unroll
        for (int nt = 0; nt < 8; nt++) {
            mx0 = fmaxf(mx0, fmaxf(S[nt][0], S[nt][1]));
            mx1 = fmaxf(mx1, fmaxf(S[nt][2], S[nt][3]));
        }
        mx0 = fmaxf(mx0, __shfl_xor_sync(0xffffffffu, mx0, 1));
        mx0 = fmaxf(mx0, __shfl_xor_sync(0xffffffffu, mx0, 2));
        mx1 = fmaxf(mx1, __shfl_xor_sync(0xffffffffu, mx1, 1));
        mx1 = fmaxf(mx1, __shfl_xor_sync(0xffffffffu, mx1, 2));

        const float mn0 = fmaxf(m0, mx0);
        const float mn1 = fmaxf(m1, mx1);
        const float cr0 = exp2f((m0 - mn0) * ESC);
        const float cr1 = exp2f((m1 - mn1) * ESC);
        m0 = mn0; m1 = mn1;
        l0 *= cr0; l1 *= cr1;
        #pragma unroll
        for (int nt = 0; nt < 8; nt++) {
            O[nt][0] *= cr0; O[nt][1] *= cr0;
            O[nt][2] *= cr1; O[nt][3] *= cr1;
        }

        float rs0 = 0.f, rs1 = 0.f;
        #pragma unroll
        for (int nt = 0; nt < 8; nt++) {
            S[nt][0] = exp2f((S[nt][0] - mn0) * ESC);
            S[nt][1] = exp2f((S[nt][1] - mn0) * ESC);
            S[nt][2] = exp2f((S[nt][2] - mn1) * ESC);
            S[nt][3] = exp2f((S[nt][3] - mn1) * ESC);
            rs0 += S[nt][0] + S[nt][1];
            rs1 += S[nt][2] + S[nt][3];
        }
        rs0 += __shfl_xor_sync(0xffffffffu, rs0, 1);
        rs0 += __shfl_xor_sync(0xffffffffu, rs0, 2);
        rs1 += __shfl_xor_sync(0xffffffffu, rs1, 1);
        rs1 += __shfl_xor_sync(0xffffffffu, rs1, 2);
        l0 += rs0; l1 += rs1;

        // ---- P fp16 fragments ----
        uint32_t pf[4][4];
        #pragma unroll
        for (int kk = 0; kk < 4; kk++) {
            pf[kk][0] = packhf(S[2*kk][0],   S[2*kk][1]);
            pf[kk][1] = packhf(S[2*kk][2],   S[2*kk][3]);
            pf[kk][2] = packhf(S[2*kk+1][0], S[2*kk+1][1]);
            pf[kk][3] = packhf(S[2*kk+1][2], S[2*kk+1][3]);
        }

        // ---- O += Pf·Vf ----
        #pragma unroll
        for (int kk = 0; kk < 4; kk++) {
            uint32_t vf[8][2];
            #pragma unroll
            for (int nd2 = 0; nd2 < 4; nd2++) {
                uint32_t r0, r1, r2, r3;
                ldsm_x4_t(r0, r1, r2, r3, bufO + TILEB + vRow + kk * 2048 + vcol[nd2]);
                vf[nd2*2][0] = r0; vf[nd2*2][1] = r1;
                vf[nd2*2+1][0] = r2; vf[nd2*2+1][1] = r3;
            }
            #pragma unroll
            for (int nd = 0; nd < 8; nd++) mma16816(O[nd], pf[kk], vf[nd]);
        }
    }

    // ---- epilogue: normalize, round to fp16, store ----
    const float i0 = 1.f / l0, i1 = 1.f / l1;
    const size_t base0 = (size_t)(b * Tseq + rowg0) * Cdim + h * HD;
    const size_t base1 = (size_t)(b * Tseq + rowg1) * Cdim + h * HD;
    #pragma unroll
    for (int nt = 0; nt < 8; nt++) {
        const int col = nt * 8 + t * 2;
        *(uint32_t*)(yf + base0 + col) = packhf(O[nt][0] * i0, O[nt][1] * i0);
        *(uint32_t*)(yf + base1 + col) = packhf(O[nt][2] * i1, O[nt][3] * i1);
    }
}

// ---------------- launch ----------------
extern "C" void kernel_launch(void* const* d_in, const int* in_sizes, int n_in,
                              void* d_out, int out_size)
{
    const float* x     = (const float*)d_in[0];
    const float* qkv_w = (const float*)d_in[1];
    const float* qkv_b = (const float*)d_in[2];
    const float* out_w = (const float*)d_in[3];
    const float* out_b = (const float*)d_in[4];
    float* out = (float*)d_out;

    __half *xf, *qkvf, *yf, *wqh, *wql, *woh, *wol;
    cudaGetSymbolAddress((void**)&xf,   g_xf);
    cudaGetSymbolAddress((void**)&qkvf, g_qkvf);
    cudaGetSymbolAddress((void**)&yf,   g_yf);
    cudaGetSymbolAddress((void**)&wqh,  g_wqh);
    cudaGetSymbolAddress((void**)&wql,  g_wql);
    cudaGetSymbolAddress((void**)&woh,  g_woh);
    cudaGetSymbolAddress((void**)&wol,  g_wol);

    cudaFuncSetAttribute(gemm_mma<true>,  cudaFuncAttributeMaxDynamicSharedMemorySize, GEMM_SMEM);
    cudaFuncSetAttribute(gemm_mma<false>, cudaFuncAttributeMaxDynamicSharedMemorySize, GEMM_SMEM);
    cudaFuncSetAttribute(attn_mma, cudaFuncAttributeMaxDynamicSharedMemorySize, ATT_SMEM);

    const int M = Mrows;   // 8192

    {
        int n4 = (M * Cdim) / 4;
        round_kernel<<<(n4 + 255) / 256, 256>>>(x, xf, n4);
    }
    splitT_kernel<<<dim3(C3 / 32, Cdim / 32), 256>>>(qkv_w, wqh, wql, Cdim, C3);
    splitT_kernel<<<dim3(Cdim / 32, Cdim / 32), 256>>>(out_w, woh, wol, Cdim, Cdim);

    // 1) QKV projection -> fp16 qkv
    gemm_mma<true><<<dim3(C3 / GBN, M / GBM), 256, GEMM_SMEM>>>(
        xf, wqh, wql, qkv_b, nullptr, qkvf, M, C3, Cdim);

    // 2) causal attention -> fp16 y
    attn_mma<<<dim3(Tseq / 128, Bsz * Hn), 256, ATT_SMEM>>>(qkvf, yf);

    // 3) output projection -> fp32 out
    gemm_mma<false><<<dim3(Cdim / GBN, M / GBM), 256, GEMM_SMEM>>>(
        yf, woh, wol, out_b, out, nullptr, M, Cdim, Cdim);
}

// round 8
// speedup vs baseline: 10.1342x; 1.2482x over previous
#include <cuda_runtime.h>
#include <cuda_fp16.h>
#include <cstdint>
#include <math.h>

#define Bsz 2
#define Tseq 4096
#define Cdim 768
#define Hn 12
#define HD 64
#define C3 (3*Cdim)
#define Mrows (Bsz*Tseq)   // 8192

// ---------------- scratch (no allocs allowed) ----------------
__device__ __align__(16) __half g_xf  [(size_t)Mrows * Cdim];
__device__ __align__(16) __half g_qkvf[(size_t)Mrows * C3];
__device__ __align__(16) __half g_yf  [(size_t)Mrows * Cdim];
__device__ __align__(16) __half g_wqf [(size_t)C3 * Cdim];   // qkv_w^T  [N,K] fp16
__device__ __align__(16) __half g_wof [(size_t)Cdim * Cdim]; // out_w^T  [N,K] fp16

// ================= portable PTX helpers =================
__device__ __forceinline__ uint32_t smem_u32(const void* p) {
    uint32_t a;
    asm("{ .reg .u64 t; cvta.to.shared.u64 t, %1; cvt.u32.u64 %0, t; }" : "=r"(a) : "l"(p));
    return a;
}
#define CP_ASYNC16(dst, src) \
    asm volatile("cp.async.cg.shared.global [%0], [%1], 16;" :: "r"(dst), "l"(src) : "memory")
#define CP_COMMIT() asm volatile("cp.async.commit_group;" ::: "memory")
#define CP_WAIT(n)  asm volatile("cp.async.wait_group %0;" :: "n"(n) : "memory")

__device__ __forceinline__ void ldsm_x4(uint32_t& r0, uint32_t& r1, uint32_t& r2, uint32_t& r3,
                                        uint32_t addr) {
    asm volatile("ldmatrix.sync.aligned.m8n8.x4.shared.b16 {%0,%1,%2,%3}, [%4];"
                 : "=r"(r0), "=r"(r1), "=r"(r2), "=r"(r3) : "r"(addr));
}
__device__ __forceinline__ void ldsm_x4_t(uint32_t& r0, uint32_t& r1, uint32_t& r2, uint32_t& r3,
                                          uint32_t addr) {
    asm volatile("ldmatrix.sync.aligned.m8n8.x4.trans.shared.b16 {%0,%1,%2,%3}, [%4];"
                 : "=r"(r0), "=r"(r1), "=r"(r2), "=r"(r3) : "r"(addr));
}
__device__ __forceinline__ void mma16816(float* d, const uint32_t* a, const uint32_t* b) {
    asm volatile(
        "mma.sync.aligned.m16n8k16.row.col.f32.f16.f16.f32 "
        "{%0,%1,%2,%3}, {%4,%5,%6,%7}, {%8,%9}, {%0,%1,%2,%3};"
        : "+f"(d[0]), "+f"(d[1]), "+f"(d[2]), "+f"(d[3])
        : "r"(a[0]), "r"(a[1]), "r"(a[2]), "r"(a[3]), "r"(b[0]), "r"(b[1]));
}
__device__ __forceinline__ uint32_t packhf(float lo, float hi) {
    uint32_t d;
    asm("cvt.rn.f16x2.f32 %0, %1, %2;" : "=r"(d) : "f"(hi), "f"(lo));
    return d;
}

// ================= fp32 -> fp16 round (elementwise) =================
__global__ __launch_bounds__(256)
void round_kernel(const float* __restrict__ in, __half* __restrict__ outp, int n4)
{
    int i4 = blockIdx.x * blockDim.x + threadIdx.x;
    if (i4 >= n4) return;
    float4 v = ((const float4*)in)[i4];
    uint2 o;
    o.x = packhf(v.x, v.y);
    o.y = packhf(v.z, v.w);
    ((uint2*)outp)[i4] = o;
}

// ============ fp32 W[K,N] -> fp16 transposed [N,K] ============
__global__ __launch_bounds__(256)
void roundT_kernel(const float* __restrict__ W, __half* __restrict__ Tf, int K, int N)
{
    __shared__ float t[32][33];
    const int n0 = blockIdx.x * 32, k0 = blockIdx.y * 32;
    const int tx = threadIdx.x & 31, ty = (threadIdx.x >> 5);
    #pragma unroll
    for (int j = 0; j < 4; j++)
        t[ty + j*8][tx] = W[(size_t)(k0 + ty + j*8) * N + n0 + tx];
    __syncthreads();
    #pragma unroll
    for (int j = 0; j < 4; j++)
        Tf[(size_t)(n0 + ty + j*8) * K + k0 + tx] = __float2half_rn(t[tx][ty + j*8]);
}

// ================= warp-MMA fp16 GEMM (swizzled, K-step 64) =================
// C[M,N] = Af[M,K] @ Bf^T + bias, B given as [N,K] (K-major).
// block tile 128x128, 8 warps (4m x 2n), warp tile 32x64. 2-stage ring, 1 sync/iter.
#define GBM 128
#define GBN 128
#define GBK 64
#define GTILE 16384              // 128 rows x 128B (SW128)
#define GSTAGE (2*GTILE)         // Af | Bf = 32768 B
#define GEMM_SMEM (2*GSTAGE)     // 65536 B

template<bool F16OUT>
__global__ __launch_bounds__(256, 2)
void gemm_mma(const __half* __restrict__ Af, const __half* __restrict__ Bf,
              const float* __restrict__ bias, float* __restrict__ C,
              __half* __restrict__ Cf,
              int M, int N, int K)
{
    extern __shared__ __align__(16) char gsm[];
    const uint32_t smBase = smem_u32(gsm);

    const int tid  = threadIdx.x;
    const int lane = tid & 31;
    const int wid  = tid >> 5;
    const int wm   = wid & 3;
    const int wn   = wid >> 2;
    const int rowBase = blockIdx.y * GBM;
    const int colBase = blockIdx.x * GBN;

    const int mat = lane >> 3, r8 = lane & 7;
    const uint32_t pat = (uint32_t)r8 << 4;     // swizzle pattern, lane-constant

    uint32_t aRow[2], bRow[4], acol[4], bcol[4];
    #pragma unroll
    for (int mt = 0; mt < 2; mt++)
        aRow[mt] = (uint32_t)(wm * 32 + mt * 16 + (mat & 1) * 8 + r8) * 128;
    #pragma unroll
    for (int nt2 = 0; nt2 < 4; nt2++)
        bRow[nt2] = (uint32_t)(wn * 64 + nt2 * 16 + (mat >> 1) * 8 + r8) * 128;
    #pragma unroll
    for (int kk = 0; kk < 4; kk++) {
        acol[kk] = (uint32_t)(kk * 32 + (mat >> 1) * 16) ^ pat;
        bcol[kk] = (uint32_t)(kk * 32 + (mat & 1) * 16) ^ pat;
    }

    float acc[2][8][4];
    #pragma unroll
    for (int i = 0; i < 2; i++)
        #pragma unroll
        for (int j = 0; j < 8; j++)
            #pragma unroll
            for (int q = 0; q < 4; q++) acc[i][j][q] = 0.f;

    const int KC = K / GBK;   // 12

    auto issue_tile = [&](int it) {
        const uint32_t stOff = (uint32_t)(it & 1) * GSTAGE;
        const int kc = it;
        #pragma unroll
        for (int i = 0; i < 8; i++) {              // 2048 chunks / 256 threads
            const int idx  = tid + i * 256;
            const int tile = idx >> 10;            // 0 Af, 1 Bf
            const int rem  = idx & 1023;
            const int r    = rem >> 3;
            const int c8   = rem & 7;
            const uint32_t dst = smBase + stOff + (uint32_t)tile * GTILE
                               + (uint32_t)(r * 128 + ((c8 * 16) ^ ((r & 7) << 4)));
            const __half* src = tile ? (Bf + (size_t)(colBase + r) * K + kc * GBK + c8 * 8)
                                     : (Af + (size_t)(rowBase + r) * K + kc * GBK + c8 * 8);
            CP_ASYNC16(dst, src);
        }
        CP_COMMIT();
    };

    issue_tile(0);

    for (int it = 0; it < KC; ++it) {
        CP_WAIT(0);
        __syncthreads();
        if (it + 1 < KC) issue_tile(it + 1);

        const uint32_t stOff = smBase + (uint32_t)(it & 1) * GSTAGE;
        #pragma unroll
        for (int kk = 0; kk < 4; kk++) {
            uint32_t af[2][4], bf[8][2];
            #pragma unroll
            for (int mt = 0; mt < 2; mt++)
                ldsm_x4(af[mt][0], af[mt][1], af[mt][2], af[mt][3],
                        stOff + aRow[mt] + acol[kk]);
            #pragma unroll
            for (int nt2 = 0; nt2 < 4; nt2++) {
                uint32_t r0, r1, r2, r3;
                ldsm_x4(r0, r1, r2, r3, stOff + GTILE + bRow[nt2] + bcol[kk]);
                bf[nt2*2][0] = r0; bf[nt2*2][1] = r1;
                bf[nt2*2+1][0] = r2; bf[nt2*2+1][1] = r3;
            }
            #pragma unroll
            for (int mt = 0; mt < 2; mt++)
                #pragma unroll
                for (int nt = 0; nt < 8; nt++)
                    mma16816(acc[mt][nt], af[mt], bf[nt]);
        }
    }

    const int g = lane >> 2, t = lane & 3;
    #pragma unroll
    for (int mt = 0; mt < 2; mt++) {
        #pragma unroll
        for (int nt = 0; nt < 8; nt++) {
            const int col = colBase + wn * 64 + nt * 8 + t * 2;
            const float b0 = bias[col], b1 = bias[col + 1];
            const int row0 = rowBase + wm * 32 + mt * 16 + g;
            float v0 = acc[mt][nt][0] + b0, v1 = acc[mt][nt][1] + b1;
            float v2 = acc[mt][nt][2] + b0, v3 = acc[mt][nt][3] + b1;
            if (F16OUT) {
                *(uint32_t*)(Cf + (size_t)row0 * N + col)       = packhf(v0, v1);
                *(uint32_t*)(Cf + (size_t)(row0 + 8) * N + col) = packhf(v2, v3);
            } else {
                *(float2*)&C[(size_t)row0 * N + col]       = make_float2(v0, v1);
                *(float2*)&C[(size_t)(row0 + 8) * N + col] = make_float2(v2, v3);
            }
        }
    }
}

// ================= tensor-core causal flash attention (fp16, swizzled) =================
// CTA: 128 queries, 8 warps x 16 rows. K-tiles of 64. D = 64. 3-stage ring, 1 sync/iter.
#define TILEB 8192                    // 64 rows x 128B (SW128)
#define BUFB  (2*TILEB)               // K, V = 16384 B
#define ATT_SMEM (3*BUFB)             // 49152 B (buffer2 doubles as Q staging: 16 KB)
#define ESC 0.18033688f               // 0.125 * log2(e)

__global__ __launch_bounds__(256, 2)
void attn_mma(const __half* __restrict__ qkv, __half* __restrict__ yf)
{
    extern __shared__ __align__(16) char sm[];
    const uint32_t smBase = smem_u32(sm);

    const int tid  = threadIdx.x;
    const int lane = tid & 31;
    const int wm   = tid >> 5;
    const int bh = blockIdx.y;
    const int b  = bh / Hn;
    const int h  = bh % Hn;
    const int q0 = (gridDim.x - 1 - blockIdx.x) * 128;   // big tiles first

    const int mat = lane >> 3, r8 = lane & 7;
    const int g = lane >> 2, t = lane & 3;
    const uint32_t pat = (uint32_t)r8 << 4;

    const int nk = q0 / 64 + 2;

    // ---- stage Q into buffer2 region (swizzled 128B rows, 16 KB) ----
    #pragma unroll
    for (int i = 0; i < 4; i++) {
        const int idx = tid + i * 256;          // 1024 chunks
        const int r   = idx >> 3;
        const int c8  = idx & 7;
        const uint32_t dst = smBase + 2u*BUFB
                           + (uint32_t)(r * 128 + ((c8 * 16) ^ ((r & 7) << 4)));
        const __half* src = qkv + (size_t)(b * Tseq + q0 + r) * C3 + h * HD + c8 * 8;
        CP_ASYNC16(dst, src);
    }
    CP_COMMIT();

    // fragment addressing (bytes)
    uint32_t kRow[4], kcol[4], qcol[4], vcol[4];
    #pragma unroll
    for (int nt2 = 0; nt2 < 4; nt2++) {
        kRow[nt2] = (uint32_t)(nt2 * 16 + (mat >> 1) * 8 + r8) * 128;
        vcol[nt2] = (uint32_t)(nt2 * 32 + (mat >> 1) * 16) ^ pat;
    }
    #pragma unroll
    for (int ks = 0; ks < 4; ks++) {
        kcol[ks] = (uint32_t)(ks * 32 + (mat & 1) * 16) ^ pat;
        qcol[ks] = (uint32_t)(ks * 32 + (mat >> 1) * 16) ^ pat;
    }
    const uint32_t qRow = (uint32_t)(wm * 16 + (mat & 1) * 8 + r8) * 128;
    const uint32_t vRow = (uint32_t)((mat & 1) * 8 + r8) * 128;

    auto fill = [&](int it) {
        const int k0 = it * 64;
        const uint32_t bufOff = (uint32_t)(it % 3) * BUFB;
        #pragma unroll
        for (int i = 0; i < 4; i++) {
            const int idx = tid + i * 256;       // 1024 chunks
            const int tile = idx >> 9;           // 0 K, 1 V
            const int r    = (idx >> 3) & 63;
            const int c8   = idx & 7;
            const uint32_t dst = smBase + bufOff + (uint32_t)tile * TILEB
                               + (uint32_t)(r * 128 + ((c8 * 16) ^ ((r & 7) << 4)));
            const __half* src = qkv + (size_t)(b * Tseq + k0 + r) * C3 + h * HD + c8 * 8
                              + (tile ? 2 * Cdim : Cdim);
            CP_ASYNC16(dst, src);
        }
        CP_COMMIT();
    };

    fill(0);
    fill(1);            // nk >= 2 always

    CP_WAIT(2);         // Q group (oldest) complete
    __syncthreads();

    uint32_t qf[4][4];
    #pragma unroll
    for (int ks = 0; ks < 4; ks++)
        ldsm_x4(qf[ks][0], qf[ks][1], qf[ks][2], qf[ks][3],
                smBase + 2u*BUFB + qRow + qcol[ks]);
    // iter-0 sync below precedes any overwrite of buffer2

    float O[8][4];
    #pragma unroll
    for (int nt = 0; nt < 8; nt++)
        #pragma unroll
        for (int q = 0; q < 4; q++) O[nt][q] = 0.f;
    float m0 = -1e30f, m1 = -1e30f, l0 = 0.f, l1 = 0.f;

    const int rowg0 = q0 + wm * 16 + g;
    const int rowg1 = rowg0 + 8;

    for (int it = 0; it < nk; ++it) {
        if (it < nk - 1) { CP_WAIT(1); } else { CP_WAIT(0); }
        __syncthreads();
        if (it + 2 < nk) fill(it + 2);

        const int k0 = it * 64;
        const uint32_t bufO = smBase + (uint32_t)(it % 3) * BUFB;

        // ---- S = Qf·Kf^T ----
        float S[8][4];
        #pragma unroll
        for (int nt = 0; nt < 8; nt++)
            #pragma unroll
            for (int q = 0; q < 4; q++) S[nt][q] = 0.f;

        #pragma unroll
        for (int ks = 0; ks < 4; ks++) {
            uint32_t kf[8][2];
            #pragma unroll
            for (int nt2 = 0; nt2 < 4; nt2++) {
                uint32_t r0, r1, r2, r3;
                ldsm_x4(r0, r1, r2, r3, bufO + kRow[nt2] + kcol[ks]);
                kf[nt2*2][0] = r0; kf[nt2*2][1] = r1;
                kf[nt2*2+1][0] = r2; kf[nt2*2+1][1] = r3;
            }
            #pragma unroll
            for (int nt = 0; nt < 8; nt++) mma16816(S[nt], qf[ks], kf[nt]);
        }

        // ---- causal mask (diagonal tiles only) ----
        if (k0 + 63 > q0 + wm * 16) {
            #pragma unroll
            for (int nt = 0; nt < 8; nt++) {
                const int c = k0 + nt * 8 + t * 2;
                if (c     > rowg0) S[nt][0] = -1e30f;
                if (c + 1 > rowg0) S[nt][1] = -1e30f;
                if (c     > rowg1) S[nt][2] = -1e30f;
                if (c + 1 > rowg1) S[nt][3] = -1e30f;
            }
        }

        // ---- online softmax ----
        float mx0 = -1e30f, mx1 = -1e30f;
        #pragma unroll
        for (int nt = 0; nt < 8; nt++) {
            mx0 = fmaxf(mx0, fmaxf(S[nt][0], S[nt][1]));
            mx1 = fmaxf(mx1, fmaxf(S[nt][2], S[nt][3]));
        }
        mx0 = fmaxf(mx0, __shfl_xor_sync(0xffffffffu, mx0, 1));
        mx0 = fmaxf(mx0, __shfl_xor_sync(0xffffffffu, mx0, 2));
        mx1 = fmaxf(mx1, __shfl_xor_sync(0xffffffffu, mx1, 1));
        mx1 = fmaxf(mx1, __shfl_xor_sync(0xffffffffu, mx1, 2));

        const float mn0 = fmaxf(m0, mx0);
        const float mn1 = fmaxf(m1, mx1);
        const float cr0 = exp2f((m0 - mn0) * ESC);
        const float cr1 = exp2f((m1 - mn1) * ESC);
        m0 = mn0; m1 = mn1;
        l0 *= cr0; l1 *= cr1;
        #pragma unroll
        for (int nt = 0; nt < 8; nt++) {
            O[nt][0] *= cr0; O[nt][1] *= cr0;
            O[nt][2] *= cr1; O[nt][3] *= cr1;
        }

        float rs0 = 0.f, rs1 = 0.f;
        #pragma unroll
        for (int nt = 0; nt < 8; nt++) {
            S[nt][0] = exp2f((S[nt][0] - mn0) * ESC);
            S[nt][1] = exp2f((S[nt][1] - mn0) * ESC);
            S[nt][2] = exp2f((S[nt][2] - mn1) * ESC);
            S[nt][3] = exp2f((S[nt][3] - mn1) * ESC);
            rs0 += S[nt][0] + S[nt][1];
            rs1 += S[nt][2] + S[nt][3];
        }
        rs0 += __shfl_xor_sync(0xffffffffu, rs0, 1);
        rs0 += __shfl_xor_sync(0xffffffffu, rs0, 2);
        rs1 += __shfl_xor_sync(0xffffffffu, rs1, 1);
        rs1 += __shfl_xor_sync(0xffffffffu, rs1, 2);
        l0 += rs0; l1 += rs1;

        // ---- P fp16 fragments ----
        uint32_t pf[4][4];
        #pragma unroll
        for (int kk = 0; kk < 4; kk++) {
            pf[kk][0] = packhf(S[2*kk][0],   S[2*kk][1]);
            pf[kk][1] = packhf(S[2*kk][2],   S[2*kk][3]);
            pf[kk][2] = packhf(S[2*kk+1][0], S[2*kk+1][1]);
            pf[kk][3] = packhf(S[2*kk+1][2], S[2*kk+1][3]);
        }

        // ---- O += Pf·Vf ----
        #pragma unroll
        for (int kk = 0; kk < 4; kk++) {
            uint32_t vf[8][2];
            #pragma unroll
            for (int nd2 = 0; nd2 < 4; nd2++) {
                uint32_t r0, r1, r2, r3;
                ldsm_x4_t(r0, r1, r2, r3, bufO + TILEB + vRow + kk * 2048 + vcol[nd2]);
                vf[nd2*2][0] = r0; vf[nd2*2][1] = r1;
                vf[nd2*2+1][0] = r2; vf[nd2*2+1][1] = r3;
            }
            #pragma unroll
            for (int nd = 0; nd < 8; nd++) mma16816(O[nd], pf[kk], vf[nd]);
        }
    }

    // ---- epilogue: normalize, round to fp16, store ----
    const float i0 = 1.f / l0, i1 = 1.f / l1;
    const size_t base0 = (size_t)(b * Tseq + rowg0) * Cdim + h * HD;
    const size_t base1 = (size_t)(b * Tseq + rowg1) * Cdim + h * HD;
    #pragma unroll
    for (int nt = 0; nt < 8; nt++) {
        const int col = nt * 8 + t * 2;
        *(uint32_t*)(yf + base0 + col) = packhf(O[nt][0] * i0, O[nt][1] * i0);
        *(uint32_t*)(yf + base1 + col) = packhf(O[nt][2] * i1, O[nt][3] * i1);
    }
}

// ---------------- launch ----------------
extern "C" void kernel_launch(void* const* d_in, const int* in_sizes, int n_in,
                              void* d_out, int out_size)
{
    const float* x     = (const float*)d_in[0];
    const float* qkv_w = (const float*)d_in[1];
    const float* qkv_b = (const float*)d_in[2];
    const float* out_w = (const float*)d_in[3];
    const float* out_b = (const float*)d_in[4];
    float* out = (float*)d_out;

    __half *xf, *qkvf, *yf, *wqf, *wof;
    cudaGetSymbolAddress((void**)&xf,   g_xf);
    cudaGetSymbolAddress((void**)&qkvf, g_qkvf);
    cudaGetSymbolAddress((void**)&yf,   g_yf);
    cudaGetSymbolAddress((void**)&wqf,  g_wqf);
    cudaGetSymbolAddress((void**)&wof,  g_wof);

    cudaFuncSetAttribute(gemm_mma<true>,  cudaFuncAttributeMaxDynamicSharedMemorySize, GEMM_SMEM);
    cudaFuncSetAttribute(gemm_mma<false>, cudaFuncAttributeMaxDynamicSharedMemorySize, GEMM_SMEM);
    cudaFuncSetAttribute(attn_mma, cudaFuncAttributeMaxDynamicSharedMemorySize, ATT_SMEM);

    const int M = Mrows;   // 8192

    {
        int n4 = (M * Cdim) / 4;
        round_kernel<<<(n4 + 255) / 256, 256>>>(x, xf, n4);
    }
    roundT_kernel<<<dim3(C3 / 32, Cdim / 32), 256>>>(qkv_w, wqf, Cdim, C3);
    roundT_kernel<<<dim3(Cdim / 32, Cdim / 32), 256>>>(out_w, wof, Cdim, Cdim);

    // 1) QKV projection -> fp16 qkv
    gemm_mma<true><<<dim3(C3 / GBN, M / GBM), 256, GEMM_SMEM>>>(
        xf, wqf, qkv_b, nullptr, qkvf, M, C3, Cdim);

    // 2) causal attention -> fp16 y
    attn_mma<<<dim3(Tseq / 128, Bsz * Hn), 256, ATT_SMEM>>>(qkvf, yf);

    // 3) output projection -> fp32 out
    gemm_mma<false><<<dim3(Cdim / GBN, M / GBM), 256, GEMM_SMEM>>>(
        yf, wof, out_b, out, nullptr, M, Cdim, Cdim);
}

// round 9
// speedup vs baseline: 10.1957x; 1.0061x over previous
#include <cuda_runtime.h>
#include <cuda_fp16.h>
#include <cstdint>
#include <math.h>

#define Bsz 2
#define Tseq 4096
#define Cdim 768
#define Hn 12
#define HD 64
#define C3 (3*Cdim)
#define Mrows (Bsz*Tseq)   // 8192

// ---------------- scratch (no allocs allowed) ----------------
__device__ __align__(16) __half g_xf  [(size_t)Mrows * Cdim];
__device__ __align__(16) __half g_qkvf[(size_t)Mrows * C3];
__device__ __align__(16) __half g_yf  [(size_t)Mrows * Cdim];
__device__ __align__(16) __half g_wqf [(size_t)C3 * Cdim];   // qkv_w^T  [N,K] fp16
__device__ __align__(16) __half g_wof [(size_t)Cdim * Cdim]; // out_w^T  [N,K] fp16

// ================= portable PTX helpers =================
__device__ __forceinline__ uint32_t smem_u32(const void* p) {
    uint32_t a;
    asm("{ .reg .u64 t; cvta.to.shared.u64 t, %1; cvt.u32.u64 %0, t; }" : "=r"(a) : "l"(p));
    return a;
}
#define CP_ASYNC16(dst, src) \
    asm volatile("cp.async.cg.shared.global [%0], [%1], 16;" :: "r"(dst), "l"(src) : "memory")
#define CP_COMMIT() asm volatile("cp.async.commit_group;" ::: "memory")
#define CP_WAIT(n)  asm volatile("cp.async.wait_group %0;" :: "n"(n) : "memory")

__device__ __forceinline__ void ldsm_x4(uint32_t& r0, uint32_t& r1, uint32_t& r2, uint32_t& r3,
                                        uint32_t addr) {
    asm volatile("ldmatrix.sync.aligned.m8n8.x4.shared.b16 {%0,%1,%2,%3}, [%4];"
                 : "=r"(r0), "=r"(r1), "=r"(r2), "=r"(r3) : "r"(addr));
}
__device__ __forceinline__ void ldsm_x4_t(uint32_t& r0, uint32_t& r1, uint32_t& r2, uint32_t& r3,
                                          uint32_t addr) {
    asm volatile("ldmatrix.sync.aligned.m8n8.x4.trans.shared.b16 {%0,%1,%2,%3}, [%4];"
                 : "=r"(r0), "=r"(r1), "=r"(r2), "=r"(r3) : "r"(addr));
}
__device__ __forceinline__ void mma16816(float* d, const uint32_t* a, const uint32_t* b) {
    asm volatile(
        "mma.sync.aligned.m16n8k16.row.col.f32.f16.f16.f32 "
        "{%0,%1,%2,%3}, {%4,%5,%6,%7}, {%8,%9}, {%0,%1,%2,%3};"
        : "+f"(d[0]), "+f"(d[1]), "+f"(d[2]), "+f"(d[3])
        : "r"(a[0]), "r"(a[1]), "r"(a[2]), "r"(a[3]), "r"(b[0]), "r"(b[1]));
}
__device__ __forceinline__ uint32_t packhf(float lo, float hi) {
    uint32_t d;
    asm("cvt.rn.f16x2.f32 %0, %1, %2;" : "=r"(d) : "f"(hi), "f"(lo));
    return d;
}

// ================= fused prep: round x + round-transpose both weights =================
// grid partition: [0, XB)              -> x fp32 -> fp16 (float4 per thread)
//                 [XB, XB+WQB)         -> qkv_w [768,2304] -> wqf [2304,768] fp16
//                 [XB+WQB, XB+WQB+WOB) -> out_w [768,768]  -> wof [768,768]  fp16
#define XB  ((Mrows*Cdim/4 + 255)/256)   // 6144
#define WQB ((C3/32)*(Cdim/32))          // 72*24 = 1728
#define WOB ((Cdim/32)*(Cdim/32))        // 576

__global__ __launch_bounds__(256)
void prep_kernel(const float* __restrict__ x, __half* __restrict__ xf,
                 const float* __restrict__ wq, __half* __restrict__ wqf,
                 const float* __restrict__ wo, __half* __restrict__ wof)
{
    const int bid = blockIdx.x;
    if (bid < XB) {
        int i4 = bid * 256 + threadIdx.x;
        if (i4 >= Mrows * Cdim / 4) return;
        float4 v = ((const float4*)x)[i4];
        uint2 o;
        o.x = packhf(v.x, v.y);
        o.y = packhf(v.z, v.w);
        ((uint2*)xf)[i4] = o;
        return;
    }
    // transpose jobs
    const float* W; __half* Tf; int K, N, bx, by;
    if (bid < XB + WQB) {
        int j = bid - XB;
        W = wq; Tf = wqf; K = Cdim; N = C3;
        bx = j % (C3/32); by = j / (C3/32);
    } else {
        int j = bid - XB - WQB;
        W = wo; Tf = wof; K = Cdim; N = Cdim;
        bx = j % (Cdim/32); by = j / (Cdim/32);
    }
    __shared__ float t[32][33];
    const int n0 = bx * 32, k0 = by * 32;
    const int tx = threadIdx.x & 31, ty = (threadIdx.x >> 5);
    #pragma unroll
    for (int j = 0; j < 4; j++)
        t[ty + j*8][tx] = W[(size_t)(k0 + ty + j*8) * N + n0 + tx];
    __syncthreads();
    #pragma unroll
    for (int j = 0; j < 4; j++)
        Tf[(size_t)(n0 + ty + j*8) * K + k0 + tx] = __float2half_rn(t[tx][ty + j*8]);
}

// ================= warp-MMA fp16 GEMM (swizzled, K-step 64, 3-stage ring) =================
// C[M,N] = Af[M,K] @ Bf^T + bias, B given as [N,K] (K-major).
// block tile 128x128, 8 warps (4m x 2n), warp tile 32x64.
#define GBM 128
#define GBN 128
#define GBK 64
#define GTILE 16384              // 128 rows x 128B (SW128)
#define GSTAGE (2*GTILE)         // Af | Bf = 32768 B
#define GEMM_SMEM (3*GSTAGE)     // 98304 B (3-stage ring)

template<bool F16OUT>
__global__ __launch_bounds__(256, 2)
void gemm_mma(const __half* __restrict__ Af, const __half* __restrict__ Bf,
              const float* __restrict__ bias, float* __restrict__ C,
              __half* __restrict__ Cf,
              int M, int N, int K)
{
    extern __shared__ __align__(16) char gsm[];
    const uint32_t smBase = smem_u32(gsm);

    const int tid  = threadIdx.x;
    const int lane = tid & 31;
    const int wid  = tid >> 5;
    const int wm   = wid & 3;
    const int wn   = wid >> 2;
    const int rowBase = blockIdx.y * GBM;
    const int colBase = blockIdx.x * GBN;

    const int mat = lane >> 3, r8 = lane & 7;
    const uint32_t pat = (uint32_t)r8 << 4;     // swizzle pattern, lane-constant

    uint32_t aRow[2], bRow[4], acol[4], bcol[4];
    #pragma unroll
    for (int mt = 0; mt < 2; mt++)
        aRow[mt] = (uint32_t)(wm * 32 + mt * 16 + (mat & 1) * 8 + r8) * 128;
    #pragma unroll
    for (int nt2 = 0; nt2 < 4; nt2++)
        bRow[nt2] = (uint32_t)(wn * 64 + nt2 * 16 + (mat >> 1) * 8 + r8) * 128;
    #pragma unroll
    for (int kk = 0; kk < 4; kk++) {
        acol[kk] = (uint32_t)(kk * 32 + (mat >> 1) * 16) ^ pat;
        bcol[kk] = (uint32_t)(kk * 32 + (mat & 1) * 16) ^ pat;
    }

    float acc[2][8][4];
    #pragma unroll
    for (int i = 0; i < 2; i++)
        #pragma unroll
        for (int j = 0; j < 8; j++)
            #pragma unroll
            for (int q = 0; q < 4; q++) acc[i][j][q] = 0.f;

    const int KC = K / GBK;   // 12

    auto issue_tile = [&](int it) {
        const uint32_t stOff = (uint32_t)(it % 3) * GSTAGE;
        const int kc = it;
        #pragma unroll
        for (int i = 0; i < 8; i++) {              // 2048 chunks / 256 threads
            const int idx  = tid + i * 256;
            const int tile = idx >> 10;            // 0 Af, 1 Bf
            const int rem  = idx & 1023;
            const int r    = rem >> 3;
            const int c8   = rem & 7;
            const uint32_t dst = smBase + stOff + (uint32_t)tile * GTILE
                               + (uint32_t)(r * 128 + ((c8 * 16) ^ ((r & 7) << 4)));
            const __half* src = tile ? (Bf + (size_t)(colBase + r) * K + kc * GBK + c8 * 8)
                                     : (Af + (size_t)(rowBase + r) * K + kc * GBK + c8 * 8);
            CP_ASYNC16(dst, src);
        }
        CP_COMMIT();
    };

    issue_tile(0);
    issue_tile(1);      // KC >= 2 always

    for (int it = 0; it < KC; ++it) {
        if (it + 1 < KC) { CP_WAIT(1); } else { CP_WAIT(0); }
        __syncthreads();              // fill(it) visible; all warps done with compute(it-1)
        if (it + 2 < KC) issue_tile(it + 2);   // overwrites buffer consumed at it-1: safe

        const uint32_t stOff = smBase + (uint32_t)(it % 3) * GSTAGE;
        #pragma unroll
        for (int kk = 0; kk < 4; kk++) {
            uint32_t af[2][4], bf[8][2];
            #pragma unroll
            for (int mt = 0; mt < 2; mt++)
                ldsm_x4(af[mt][0], af[mt][1], af[mt][2], af[mt][3],
                        stOff + aRow[mt] + acol[kk]);
            #pragma unroll
            for (int nt2 = 0; nt2 < 4; nt2++) {
                uint32_t r0, r1, r2, r3;
                ldsm_x4(r0, r1, r2, r3, stOff + GTILE + bRow[nt2] + bcol[kk]);
                bf[nt2*2][0] = r0; bf[nt2*2][1] = r1;
                bf[nt2*2+1][0] = r2; bf[nt2*2+1][1] = r3;
            }
            #pragma unroll
            for (int mt = 0; mt < 2; mt++)
                #pragma unroll
                for (int nt = 0; nt < 8; nt++)
                    mma16816(acc[mt][nt], af[mt], bf[nt]);
        }
    }

    const int g = lane >> 2, t = lane & 3;
    #pragma unroll
    for (int mt = 0; mt < 2; mt++) {
        #pragma unroll
        for (int nt = 0; nt < 8; nt++) {
            const int col = colBase + wn * 64 + nt * 8 + t * 2;
            const float b0 = bias[col], b1 = bias[col + 1];
            const int row0 = rowBase + wm * 32 + mt * 16 + g;
            float v0 = acc[mt][nt][0] + b0, v1 = acc[mt][nt][1] + b1;
            float v2 = acc[mt][nt][2] + b0, v3 = acc[mt][nt][3] + b1;
            if (F16OUT) {
                *(uint32_t*)(Cf + (size_t)row0 * N + col)       = packhf(v0, v1);
                *(uint32_t*)(Cf + (size_t)(row0 + 8) * N + col) = packhf(v2, v3);
            } else {
                *(float2*)&C[(size_t)row0 * N + col]       = make_float2(v0, v1);
                *(float2*)&C[(size_t)(row0 + 8) * N + col] = make_float2(v2, v3);
            }
        }
    }
}

// ================= tensor-core causal flash attention (fp16, swizzled) =================
// CTA: 128 queries, 8 warps x 16 rows. K-tiles of 64. D = 64. 3-stage ring, 1 sync/iter.
#define TILEB 8192                    // 64 rows x 128B (SW128)
#define BUFB  (2*TILEB)               // K, V = 16384 B
#define ATT_SMEM (3*BUFB)             // 49152 B (buffer2 doubles as Q staging: 16 KB)
#define ESC 0.18033688f               // 0.125 * log2(e)

__global__ __launch_bounds__(256, 2)
void attn_mma(const __half* __restrict__ qkv, __half* __restrict__ yf)
{
    extern __shared__ __align__(16) char sm[];
    const uint32_t smBase = smem_u32(sm);

    const int tid  = threadIdx.x;
    const int lane = tid & 31;
    const int wm   = tid >> 5;
    const int bh = blockIdx.y;
    const int b  = bh / Hn;
    const int h  = bh % Hn;
    const int q0 = (gridDim.x - 1 - blockIdx.x) * 128;   // big tiles first

    const int mat = lane >> 3, r8 = lane & 7;
    const int g = lane >> 2, t = lane & 3;
    const uint32_t pat = (uint32_t)r8 << 4;

    const int nk = q0 / 64 + 2;

    // ---- stage Q into buffer2 region (swizzled 128B rows, 16 KB) ----
    #pragma unroll
    for (int i = 0; i < 4; i++) {
        const int idx = tid + i * 256;          // 1024 chunks
        const int r   = idx >> 3;
        const int c8  = idx & 7;
        const uint32_t dst = smBase + 2u*BUFB
                           + (uint32_t)(r * 128 + ((c8 * 16) ^ ((r & 7) << 4)));
        const __half* src = qkv + (size_t)(b * Tseq + q0 + r) * C3 + h * HD + c8 * 8;
        CP_ASYNC16(dst, src);
    }
    CP_COMMIT();

    // fragment addressing (bytes)
    uint32_t kRow[4], kcol[4], qcol[4], vcol[4];
    #pragma unroll
    for (int nt2 = 0; nt2 < 4; nt2++) {
        kRow[nt2] = (uint32_t)(nt2 * 16 + (mat >> 1) * 8 + r8) * 128;
        vcol[nt2] = (uint32_t)(nt2 * 32 + (mat >> 1) * 16) ^ pat;
    }
    #pragma unroll
    for (int ks = 0; ks < 4; ks++) {
        kcol[ks] = (uint32_t)(ks * 32 + (mat & 1) * 16) ^ pat;
        qcol[ks] = (uint32_t)(ks * 32 + (mat >> 1) * 16) ^ pat;
    }
    const uint32_t qRow = (uint32_t)(wm * 16 + (mat & 1) * 8 + r8) * 128;
    const uint32_t vRow = (uint32_t)((mat & 1) * 8 + r8) * 128;

    auto fill = [&](int it) {
        const int k0 = it * 64;
        const uint32_t bufOff = (uint32_t)(it % 3) * BUFB;
        #pragma unroll
        for (int i = 0; i < 4; i++) {
            const int idx = tid + i * 256;       // 1024 chunks
            const int tile = idx >> 9;           // 0 K, 1 V
            const int r    = (idx >> 3) & 63;
            const int c8   = idx & 7;
            const uint32_t dst = smBase + bufOff + (uint32_t)tile * TILEB
                               + (uint32_t)(r * 128 + ((c8 * 16) ^ ((r & 7) << 4)));
            const __half* src = qkv + (size_t)(b * Tseq + k0 + r) * C3 + h * HD + c8 * 8
                              + (tile ? 2 * Cdim : Cdim);
            CP_ASYNC16(dst, src);
        }
        CP_COMMIT();
    };

    fill(0);
    fill(1);            // nk >= 2 always

    CP_WAIT(2);         // Q group (oldest) complete
    __syncthreads();

    uint32_t qf[4][4];
    #pragma unroll
    for (int ks = 0; ks < 4; ks++)
        ldsm_x4(qf[ks][0], qf[ks][1], qf[ks][2], qf[ks][3],
                smBase + 2u*BUFB + qRow + qcol[ks]);
    // iter-0 sync below precedes any overwrite of buffer2

    float O[8][4];
    #pragma unroll
    for (int nt = 0; nt < 8; nt++)
        #pragma unroll
        for (int q = 0; q < 4; q++) O[nt][q] = 0.f;
    float m0 = -1e30f, m1 = -1e30f, l0 = 0.f, l1 = 0.f;

    const int rowg0 = q0 + wm * 16 + g;
    const int rowg1 = rowg0 + 8;

    for (int it = 0; it < nk; ++it) {
        if (it < nk - 1) { CP_WAIT(1); } else { CP_WAIT(0); }
        __syncthreads();
        if (it + 2 < nk) fill(it + 2);

        const int k0 = it * 64;
        const uint32_t bufO = smBase + (uint32_t)(it % 3) * BUFB;

        // ---- S = Qf·Kf^T ----
        float S[8][4];
        #pragma unroll
        for (int nt = 0; nt < 8; nt++)
            #pragma unroll
            for (int q = 0; q < 4; q++) S[nt][q] = 0.f;

        #pragma unroll
        for (int ks = 0; ks < 4; ks++) {
            uint32_t kf[8][2];
            #pragma unroll
            for (int nt2 = 0; nt2 < 4; nt2++) {
                uint32_t r0, r1, r2, r3;
                ldsm_x4(r0, r1, r2, r3, bufO + kRow[nt2] + kcol[ks]);
                kf[nt2*2][0] = r0; kf[nt2*2][1] = r1;
                kf[nt2*2+1][0] = r2; kf[nt2*2+1][1] = r3;
            }
            #pragma unroll
            for (int nt = 0; nt < 8; nt++) mma16816(S[nt], qf[ks], kf[nt]);
        }

        // ---- causal mask (diagonal tiles only) ----
        if (k0 + 63 > q0 + wm * 16) {
            #pragma unroll
            for (int nt = 0; nt < 8; nt++) {
                const int c = k0 + nt * 8 + t * 2;
                if (c     > rowg0) S[nt][0] = -1e30f;
                if (c + 1 > rowg0) S[nt][1] = -1e30f;
                if (c     > rowg1) S[nt][2] = -1e30f;
                if (c + 1 > rowg1) S[nt][3] = -1e30f;
            }
        }

        // ---- online softmax ----
        float mx0 = -1e30f, mx1 = -1e30f;
        #pragma unroll
        for (int nt = 0; nt < 8; nt++) {
            mx0 = fmaxf(mx0, fmaxf(S[nt][0], S[nt][1]));
            mx1 = fmaxf(mx1, fmaxf(S[nt][2], S[nt][3]));
        }
        mx0 = fmaxf(mx0, __shfl_xor_sync(0xffffffffu, mx0, 1));
        mx0 = fmaxf(mx0, __shfl_xor_sync(0xffffffffu, mx0, 2));
        mx1 = fmaxf(mx1, __shfl_xor_sync(0xffffffffu, mx1, 1));
        mx1 = fmaxf(mx1, __shfl_xor_sync(0xffffffffu, mx1, 2));

        const float mn0 = fmaxf(m0, mx0);
        const float mn1 = fmaxf(m1, mx1);
        const float cr0 = exp2f((m0 - mn0) * ESC);
        const float cr1 = exp2f((m1 - mn1) * ESC);
        m0 = mn0; m1 = mn1;
        l0 *= cr0; l1 *= cr1;
        #pragma unroll
        for (int nt = 0; nt < 8; nt++) {
            O[nt][0] *= cr0; O[nt][1] *= cr0;
            O[nt][2] *= cr1; O[nt][3] *= cr1;
        }

        float rs0 = 0.f, rs1 = 0.f;
        #pragma unroll
        for (int nt = 0; nt < 8; nt++) {
            S[nt][0] = exp2f((S[nt][0] - mn0) * ESC);
            S[nt][1] = exp2f((S[nt][1] - mn0) * ESC);
            S[nt][2] = exp2f((S[nt][2] - mn1) * ESC);
            S[nt][3] = exp2f((S[nt][3] - mn1) * ESC);
            rs0 += S[nt][0] + S[nt][1];
            rs1 += S[nt][2] + S[nt][3];
        }
        rs0 += __shfl_xor_sync(0xffffffffu, rs0, 1);
        rs0 += __shfl_xor_sync(0xffffffffu, rs0, 2);
        rs1 += __shfl_xor_sync(0xffffffffu, rs1, 1);
        rs1 += __shfl_xor_sync(0xffffffffu, rs1, 2);
        l0 += rs0; l1 += rs1;

        // ---- P fp16 fragments ----
        uint32_t pf[4][4];
        #pragma unroll
        for (int kk = 0; kk < 4; kk++) {
            pf[kk][0] = packhf(S[2*kk][0],   S[2*kk][1]);
            pf[kk][1] = packhf(S[2*kk][2],   S[2*kk][3]);
            pf[kk][2] = packhf(S[2*kk+1][0], S[2*kk+1][1]);
            pf[kk][3] = packhf(S[2*kk+1][2], S[2*kk+1][3]);
        }

        // ---- O += Pf·Vf ----
        #pragma unroll
        for (int kk = 0; kk < 4; kk++) {
            uint32_t vf[8][2];
            #pragma unroll
            for (int nd2 = 0; nd2 < 4; nd2++) {
                uint32_t r0, r1, r2, r3;
                ldsm_x4_t(r0, r1, r2, r3, bufO + TILEB + vRow + kk * 2048 + vcol[nd2]);
                vf[nd2*2][0] = r0; vf[nd2*2][1] = r1;
                vf[nd2*2+1][0] = r2; vf[nd2*2+1][1] = r3;
            }
            #pragma unroll
            for (int nd = 0; nd < 8; nd++) mma16816(O[nd], pf[kk], vf[nd]);
        }
    }

    // ---- epilogue: normalize, round to fp16, store ----
    const float i0 = 1.f / l0, i1 = 1.f / l1;
    const size_t base0 = (size_t)(b * Tseq + rowg0) * Cdim + h * HD;
    const size_t base1 = (size_t)(b * Tseq + rowg1) * Cdim + h * HD;
    #pragma unroll
    for (int nt = 0; nt < 8; nt++) {
        const int col = nt * 8 + t * 2;
        *(uint32_t*)(yf + base0 + col) = packhf(O[nt][0] * i0, O[nt][1] * i0);
        *(uint32_t*)(yf + base1 + col) = packhf(O[nt][2] * i1, O[nt][3] * i1);
    }
}

// ---------------- launch ----------------
extern "C" void kernel_launch(void* const* d_in, const int* in_sizes, int n_in,
                              void* d_out, int out_size)
{
    const float* x     = (const float*)d_in[0];
    const float* qkv_w = (const float*)d_in[1];
    const float* qkv_b = (const float*)d_in[2];
    const float* out_w = (const float*)d_in[3];
    const float* out_b = (const float*)d_in[4];
    float* out = (float*)d_out;

    __half *xf, *qkvf, *yf, *wqf, *wof;
    cudaGetSymbolAddress((void**)&xf,   g_xf);
    cudaGetSymbolAddress((void**)&qkvf, g_qkvf);
    cudaGetSymbolAddress((void**)&yf,   g_yf);
    cudaGetSymbolAddress((void**)&wqf,  g_wqf);
    cudaGetSymbolAddress((void**)&wof,  g_wof);

    cudaFuncSetAttribute(gemm_mma<true>,  cudaFuncAttributeMaxDynamicSharedMemorySize, GEMM_SMEM);
    cudaFuncSetAttribute(gemm_mma<false>, cudaFuncAttributeMaxDynamicSharedMemorySize, GEMM_SMEM);
    cudaFuncSetAttribute(attn_mma, cudaFuncAttributeMaxDynamicSharedMemorySize, ATT_SMEM);

    const int M = Mrows;   // 8192

    // 0) fused prep: round x, round-transpose both weights (one launch)
    prep_kernel<<<XB + WQB + WOB, 256>>>(x, xf, qkv_w, wqf, out_w, wof);

    // 1) QKV projection -> fp16 qkv
    gemm_mma<true><<<dim3(C3 / GBN, M / GBM), 256, GEMM_SMEM>>>(
        xf, wqf, qkv_b, nullptr, qkvf, M, C3, Cdim);

    // 2) causal attention -> fp16 y
    attn_mma<<<dim3(Tseq / 128, Bsz * Hn), 256, ATT_SMEM>>>(qkvf, yf);

    // 3) output projection -> fp32 out
    gemm_mma<false><<<dim3(Cdim / GBN, M / GBM), 256, GEMM_SMEM>>>(
        yf, wof, out_b, out, nullptr, M, Cdim, Cdim);
}

// round 10
// speedup vs baseline: 10.7290x; 1.0523x over previous
#include <cuda_runtime.h>
#include <cuda_fp16.h>
#include <cstdint>
#include <math.h>

#define Bsz 2
#define Tseq 4096
#define Cdim 768
#define Hn 12
#define HD 64
#define C3 (3*Cdim)
#define Mrows (Bsz*Tseq)   // 8192

// ---------------- scratch (no allocs allowed) ----------------
__device__ __align__(16) __half g_xf  [(size_t)Mrows * Cdim];
__device__ __align__(16) __half g_qkvf[(size_t)Mrows * C3];
__device__ __align__(16) __half g_yf  [(size_t)Mrows * Cdim];
__device__ __align__(16) __half g_wqf [(size_t)C3 * Cdim];   // qkv_w^T  [N,K] fp16
__device__ __align__(16) __half g_wof [(size_t)Cdim * Cdim]; // out_w^T  [N,K] fp16

// ================= portable PTX helpers =================
__device__ __forceinline__ uint32_t smem_u32(const void* p) {
    uint32_t a;
    asm("{ .reg .u64 t; cvta.to.shared.u64 t, %1; cvt.u32.u64 %0, t; }" : "=r"(a) : "l"(p));
    return a;
}
#define CP_ASYNC16(dst, src) \
    asm volatile("cp.async.cg.shared.global [%0], [%1], 16;" :: "r"(dst), "l"(src) : "memory")
#define CP_COMMIT() asm volatile("cp.async.commit_group;" ::: "memory")
#define CP_WAIT(n)  asm volatile("cp.async.wait_group %0;" :: "n"(n) : "memory")

__device__ __forceinline__ void ldsm_x4(uint32_t& r0, uint32_t& r1, uint32_t& r2, uint32_t& r3,
                                        uint32_t addr) {
    asm volatile("ldmatrix.sync.aligned.m8n8.x4.shared.b16 {%0,%1,%2,%3}, [%4];"
                 : "=r"(r0), "=r"(r1), "=r"(r2), "=r"(r3) : "r"(addr));
}
__device__ __forceinline__ void ldsm_x4_t(uint32_t& r0, uint32_t& r1, uint32_t& r2, uint32_t& r3,
                                          uint32_t addr) {
    asm volatile("ldmatrix.sync.aligned.m8n8.x4.trans.shared.b16 {%0,%1,%2,%3}, [%4];"
                 : "=r"(r0), "=r"(r1), "=r"(r2), "=r"(r3) : "r"(addr));
}
__device__ __forceinline__ void mma16816(float* d, const uint32_t* a, const uint32_t* b) {
    asm volatile(
        "mma.sync.aligned.m16n8k16.row.col.f32.f16.f16.f32 "
        "{%0,%1,%2,%3}, {%4,%5,%6,%7}, {%8,%9}, {%0,%1,%2,%3};"
        : "+f"(d[0]), "+f"(d[1]), "+f"(d[2]), "+f"(d[3])
        : "r"(a[0]), "r"(a[1]), "r"(a[2]), "r"(a[3]), "r"(b[0]), "r"(b[1]));
}
__device__ __forceinline__ uint32_t packhf(float lo, float hi) {
    uint32_t d;
    asm("cvt.rn.f16x2.f32 %0, %1, %2;" : "=r"(d) : "f"(hi), "f"(lo));
    return d;
}
__device__ __forceinline__ uint32_t ex2_f16x2(uint32_t a) {
    uint32_t d;
    asm("ex2.approx.f16x2 %0, %1;" : "=r"(d) : "r"(a));
    return d;
}

// ================= fused prep: round x + round-transpose both weights =================
#define XB  ((Mrows*Cdim/4 + 255)/256)   // 6144
#define WQB ((C3/32)*(Cdim/32))          // 1728
#define WOB ((Cdim/32)*(Cdim/32))        // 576

__global__ __launch_bounds__(256)
void prep_kernel(const float* __restrict__ x, __half* __restrict__ xf,
                 const float* __restrict__ wq, __half* __restrict__ wqf,
                 const float* __restrict__ wo, __half* __restrict__ wof)
{
    const int bid = blockIdx.x;
    if (bid < XB) {
        int i4 = bid * 256 + threadIdx.x;
        if (i4 >= Mrows * Cdim / 4) return;
        float4 v = ((const float4*)x)[i4];
        uint2 o;
        o.x = packhf(v.x, v.y);
        o.y = packhf(v.z, v.w);
        ((uint2*)xf)[i4] = o;
        return;
    }
    const float* W; __half* Tf; int K, N, bx, by;
    if (bid < XB + WQB) {
        int j = bid - XB;
        W = wq; Tf = wqf; K = Cdim; N = C3;
        bx = j % (C3/32); by = j / (C3/32);
    } else {
        int j = bid - XB - WQB;
        W = wo; Tf = wof; K = Cdim; N = Cdim;
        bx = j % (Cdim/32); by = j / (Cdim/32);
    }
    __shared__ float t[32][33];
    const int n0 = bx * 32, k0 = by * 32;
    const int tx = threadIdx.x & 31, ty = (threadIdx.x >> 5);
    #pragma unroll
    for (int j = 0; j < 4; j++)
        t[ty + j*8][tx] = W[(size_t)(k0 + ty + j*8) * N + n0 + tx];
    __syncthreads();
    #pragma unroll
    for (int j = 0; j < 4; j++)
        Tf[(size_t)(n0 + ty + j*8) * K + k0 + tx] = __float2half_rn(t[tx][ty + j*8]);
}

// ================= warp-MMA fp16 GEMM (swizzled, K-step 64, 3-stage ring) =================
#define GBM 128
#define GBN 128
#define GBK 64
#define GTILE 16384              // 128 rows x 128B (SW128)
#define GSTAGE (2*GTILE)         // Af | Bf = 32768 B
#define GEMM_SMEM (3*GSTAGE)     // 98304 B

template<bool F16OUT>
__global__ __launch_bounds__(256, 2)
void gemm_mma(const __half* __restrict__ Af, const __half* __restrict__ Bf,
              const float* __restrict__ bias, float* __restrict__ C,
              __half* __restrict__ Cf,
              int M, int N, int K)
{
    extern __shared__ __align__(16) char gsm[];
    const uint32_t smBase = smem_u32(gsm);

    const int tid  = threadIdx.x;
    const int lane = tid & 31;
    const int wid  = tid >> 5;
    const int wm   = wid & 3;
    const int wn   = wid >> 2;
    const int rowBase = blockIdx.y * GBM;
    const int colBase = blockIdx.x * GBN;

    const int mat = lane >> 3, r8 = lane & 7;
    const uint32_t pat = (uint32_t)r8 << 4;

    uint32_t aRow[2], bRow[4], acol[4], bcol[4];
    #pragma unroll
    for (int mt = 0; mt < 2; mt++)
        aRow[mt] = (uint32_t)(wm * 32 + mt * 16 + (mat & 1) * 8 + r8) * 128;
    #pragma unroll
    for (int nt2 = 0; nt2 < 4; nt2++)
        bRow[nt2] = (uint32_t)(wn * 64 + nt2 * 16 + (mat >> 1) * 8 + r8) * 128;
    #pragma unroll
    for (int kk = 0; kk < 4; kk++) {
        acol[kk] = (uint32_t)(kk * 32 + (mat >> 1) * 16) ^ pat;
        bcol[kk] = (uint32_t)(kk * 32 + (mat & 1) * 16) ^ pat;
    }

    float acc[2][8][4];
    #pragma unroll
    for (int i = 0; i < 2; i++)
        #pragma unroll
        for (int j = 0; j < 8; j++)
            #pragma unroll
            for (int q = 0; q < 4; q++) acc[i][j][q] = 0.f;

    const int KC = K / GBK;   // 12

    auto issue_tile = [&](int it) {
        const uint32_t stOff = (uint32_t)(it % 3) * GSTAGE;
        const int kc = it;
        #pragma unroll
        for (int i = 0; i < 8; i++) {
            const int idx  = tid + i * 256;
            const int tile = idx >> 10;
            const int rem  = idx & 1023;
            const int r    = rem >> 3;
            const int c8   = rem & 7;
            const uint32_t dst = smBase + stOff + (uint32_t)tile * GTILE
                               + (uint32_t)(r * 128 + ((c8 * 16) ^ ((r & 7) << 4)));
            const __half* src = tile ? (Bf + (size_t)(colBase + r) * K + kc * GBK + c8 * 8)
                                     : (Af + (size_t)(rowBase + r) * K + kc * GBK + c8 * 8);
            CP_ASYNC16(dst, src);
        }
        CP_COMMIT();
    };

    issue_tile(0);
    issue_tile(1);

    for (int it = 0; it < KC; ++it) {
        if (it + 1 < KC) { CP_WAIT(1); } else { CP_WAIT(0); }
        __syncthreads();
        if (it + 2 < KC) issue_tile(it + 2);

        const uint32_t stOff = smBase + (uint32_t)(it % 3) * GSTAGE;
        #pragma unroll
        for (int kk = 0; kk < 4; kk++) {
            uint32_t af[2][4], bf[8][2];
            #pragma unroll
            for (int mt = 0; mt < 2; mt++)
                ldsm_x4(af[mt][0], af[mt][1], af[mt][2], af[mt][3],
                        stOff + aRow[mt] + acol[kk]);
            #pragma unroll
            for (int nt2 = 0; nt2 < 4; nt2++) {
                uint32_t r0, r1, r2, r3;
                ldsm_x4(r0, r1, r2, r3, stOff + GTILE + bRow[nt2] + bcol[kk]);
                bf[nt2*2][0] = r0; bf[nt2*2][1] = r1;
                bf[nt2*2+1][0] = r2; bf[nt2*2+1][1] = r3;
            }
            #pragma unroll
            for (int mt = 0; mt < 2; mt++)
                #pragma unroll
                for (int nt = 0; nt < 8; nt++)
                    mma16816(acc[mt][nt], af[mt], bf[nt]);
        }
    }

    const int g = lane >> 2, t = lane & 3;
    #pragma unroll
    for (int mt = 0; mt < 2; mt++) {
        #pragma unroll
        for (int nt = 0; nt < 8; nt++) {
            const int col = colBase + wn * 64 + nt * 8 + t * 2;
            const float b0 = bias[col], b1 = bias[col + 1];
            const int row0 = rowBase + wm * 32 + mt * 16 + g;
            float v0 = acc[mt][nt][0] + b0, v1 = acc[mt][nt][1] + b1;
            float v2 = acc[mt][nt][2] + b0, v3 = acc[mt][nt][3] + b1;
            if (F16OUT) {
                *(uint32_t*)(Cf + (size_t)row0 * N + col)       = packhf(v0, v1);
                *(uint32_t*)(Cf + (size_t)(row0 + 8) * N + col) = packhf(v2, v3);
            } else {
                *(float2*)&C[(size_t)row0 * N + col]       = make_float2(v0, v1);
                *(float2*)&C[(size_t)(row0 + 8) * N + col] = make_float2(v2, v3);
            }
        }
    }
}

// ================= tensor-core causal flash attention (fp16, swizzled) =================
// CTA: 128 queries, 8 warps x 16 rows. K-tiles of 64. D = 64. 3-stage ring.
// Softmax: exp via ex2.approx.f16x2 straight into P fragments; row-sum l via
// MMA against a ones-fragment (exact fp32 sum of the fp16 P actually used).
#define TILEB 8192                    // 64 rows x 128B (SW128)
#define BUFB  (2*TILEB)               // K, V = 16384 B
#define ATT_SMEM (3*BUFB)             // 49152 B (buffer2 doubles as Q staging)
#define ESC 0.18033688f               // 0.125 * log2(e)

__global__ __launch_bounds__(256, 2)
void attn_mma(const __half* __restrict__ qkv, __half* __restrict__ yf)
{
    extern __shared__ __align__(16) char sm[];
    const uint32_t smBase = smem_u32(sm);

    const int tid  = threadIdx.x;
    const int lane = tid & 31;
    const int wm   = tid >> 5;
    const int bh = blockIdx.y;
    const int b  = bh / Hn;
    const int h  = bh % Hn;
    const int q0 = (gridDim.x - 1 - blockIdx.x) * 128;   // big tiles first

    const int mat = lane >> 3, r8 = lane & 7;
    const int g = lane >> 2, t = lane & 3;
    const uint32_t pat = (uint32_t)r8 << 4;

    const int nk = q0 / 64 + 2;

    // ---- stage Q into buffer2 region ----
    #pragma unroll
    for (int i = 0; i < 4; i++) {
        const int idx = tid + i * 256;
        const int r   = idx >> 3;
        const int c8  = idx & 7;
        const uint32_t dst = smBase + 2u*BUFB
                           + (uint32_t)(r * 128 + ((c8 * 16) ^ ((r & 7) << 4)));
        const __half* src = qkv + (size_t)(b * Tseq + q0 + r) * C3 + h * HD + c8 * 8;
        CP_ASYNC16(dst, src);
    }
    CP_COMMIT();

    uint32_t kRow[4], kcol[4], qcol[4], vcol[4];
    #pragma unroll
    for (int nt2 = 0; nt2 < 4; nt2++) {
        kRow[nt2] = (uint32_t)(nt2 * 16 + (mat >> 1) * 8 + r8) * 128;
        vcol[nt2] = (uint32_t)(nt2 * 32 + (mat >> 1) * 16) ^ pat;
    }
    #pragma unroll
    for (int ks = 0; ks < 4; ks++) {
        kcol[ks] = (uint32_t)(ks * 32 + (mat & 1) * 16) ^ pat;
        qcol[ks] = (uint32_t)(ks * 32 + (mat >> 1) * 16) ^ pat;
    }
    const uint32_t qRow = (uint32_t)(wm * 16 + (mat & 1) * 8 + r8) * 128;
    const uint32_t vRow = (uint32_t)((mat & 1) * 8 + r8) * 128;

    auto fill = [&](int it) {
        const int k0 = it * 64;
        const uint32_t bufOff = (uint32_t)(it % 3) * BUFB;
        #pragma unroll
        for (int i = 0; i < 4; i++) {
            const int idx = tid + i * 256;
            const int tile = idx >> 9;
            const int r    = (idx >> 3) & 63;
            const int c8   = idx & 7;
            const uint32_t dst = smBase + bufOff + (uint32_t)tile * TILEB
                               + (uint32_t)(r * 128 + ((c8 * 16) ^ ((r & 7) << 4)));
            const __half* src = qkv + (size_t)(b * Tseq + k0 + r) * C3 + h * HD + c8 * 8
                              + (tile ? 2 * Cdim : Cdim);
            CP_ASYNC16(dst, src);
        }
        CP_COMMIT();
    };

    fill(0);
    fill(1);

    CP_WAIT(2);
    __syncthreads();

    uint32_t qf[4][4];
    #pragma unroll
    for (int ks = 0; ks < 4; ks++)
        ldsm_x4(qf[ks][0], qf[ks][1], qf[ks][2], qf[ks][3],
                smBase + 2u*BUFB + qRow + qcol[ks]);

    float O[8][4];
    #pragma unroll
    for (int nt = 0; nt < 8; nt++)
        #pragma unroll
        for (int q = 0; q < 4; q++) O[nt][q] = 0.f;
    float m0 = -1e30f, m1 = -1e30f, l0 = 0.f, l1 = 0.f;

    const int rowg0 = q0 + wm * 16 + g;
    const int rowg1 = rowg0 + 8;
    const uint32_t onesb[2] = {0x3C003C00u, 0x3C003C00u};   // fp16 1.0 x4

    for (int it = 0; it < nk; ++it) {
        if (it < nk - 1) { CP_WAIT(1); } else { CP_WAIT(0); }
        __syncthreads();
        if (it + 2 < nk) fill(it + 2);

        const int k0 = it * 64;
        const uint32_t bufO = smBase + (uint32_t)(it % 3) * BUFB;

        // ---- S = Qf·Kf^T ----
        float S[8][4];
        #pragma unroll
        for (int nt = 0; nt < 8; nt++)
            #pragma unroll
            for (int q = 0; q < 4; q++) S[nt][q] = 0.f;

        #pragma unroll
        for (int ks = 0; ks < 4; ks++) {
            uint32_t kf[8][2];
            #pragma unroll
            for (int nt2 = 0; nt2 < 4; nt2++) {
                uint32_t r0, r1, r2, r3;
                ldsm_x4(r0, r1, r2, r3, bufO + kRow[nt2] + kcol[ks]);
                kf[nt2*2][0] = r0; kf[nt2*2][1] = r1;
                kf[nt2*2+1][0] = r2; kf[nt2*2+1][1] = r3;
            }
            #pragma unroll
            for (int nt = 0; nt < 8; nt++) mma16816(S[nt], qf[ks], kf[nt]);
        }

        // ---- causal mask (diagonal tiles only) ----
        if (k0 + 63 > q0 + wm * 16) {
            #pragma unroll
            for (int nt = 0; nt < 8; nt++) {
                const int c = k0 + nt * 8 + t * 2;
                if (c     > rowg0) S[nt][0] = -1e30f;
                if (c + 1 > rowg0) S[nt][1] = -1e30f;
                if (c     > rowg1) S[nt][2] = -1e30f;
                if (c + 1 > rowg1) S[nt][3] = -1e30f;
            }
        }

        // ---- online softmax: max ----
        float mx0 = -1e30f, mx1 = -1e30f;
        #pragma unroll
        for (int nt = 0; nt < 8; nt++) {
            mx0 = fmaxf(mx0, fmaxf(S[nt][0], S[nt][1]));
            mx1 = fmaxf(mx1, fmaxf(S[nt][2], S[nt][3]));
        }
        mx0 = fmaxf(mx0, __shfl_xor_sync(0xffffffffu, mx0, 1));
        mx0 = fmaxf(mx0, __shfl_xor_sync(0xffffffffu, mx0, 2));
        mx1 = fmaxf(mx1, __shfl_xor_sync(0xffffffffu, mx1, 1));
        mx1 = fmaxf(mx1, __shfl_xor_sync(0xffffffffu, mx1, 2));

        const float mn0 = fmaxf(m0, mx0);
        const float mn1 = fmaxf(m1, mx1);
        const float cr0 = exp2f((m0 - mn0) * ESC);
        const float cr1 = exp2f((m1 - mn1) * ESC);
        m0 = mn0; m1 = mn1;
        #pragma unroll
        for (int nt = 0; nt < 8; nt++) {
            O[nt][0] *= cr0; O[nt][1] *= cr0;
            O[nt][2] *= cr1; O[nt][3] *= cr1;
        }

        // ---- P fragments via f16x2 exp: pf = 2^(S*ESC - mn*ESC) ----
        const float nE0 = mn0 * ESC, nE1 = mn1 * ESC;
        uint32_t pf[4][4];
        #pragma unroll
        for (int kk = 0; kk < 4; kk++) {
            pf[kk][0] = ex2_f16x2(packhf(fmaf(S[2*kk][0],   ESC, -nE0), fmaf(S[2*kk][1],   ESC, -nE0)));
            pf[kk][1] = ex2_f16x2(packhf(fmaf(S[2*kk][2],   ESC, -nE1), fmaf(S[2*kk][3],   ESC, -nE1)));
            pf[kk][2] = ex2_f16x2(packhf(fmaf(S[2*kk+1][0], ESC, -nE0), fmaf(S[2*kk+1][1], ESC, -nE0)));
            pf[kk][3] = ex2_f16x2(packhf(fmaf(S[2*kk+1][2], ESC, -nE1), fmaf(S[2*kk+1][3], ESC, -nE1)));
        }

        // ---- row sums via MMA with ones-fragment (exact fp32 sum of fp16 P) ----
        float lac[4] = {0.f, 0.f, 0.f, 0.f};
        #pragma unroll
        for (int kk = 0; kk < 4; kk++) mma16816(lac, pf[kk], onesb);
        l0 = l0 * cr0 + lac[0];
        l1 = l1 * cr1 + lac[2];

        // ---- O += Pf·Vf ----
        #pragma unroll
        for (int kk = 0; kk < 4; kk++) {
            uint32_t vf[8][2];
            #pragma unroll
            for (int nd2 = 0; nd2 < 4; nd2++) {
                uint32_t r0, r1, r2, r3;
                ldsm_x4_t(r0, r1, r2, r3, bufO + TILEB + vRow + kk * 2048 + vcol[nd2]);
                vf[nd2*2][0] = r0; vf[nd2*2][1] = r1;
                vf[nd2*2+1][0] = r2; vf[nd2*2+1][1] = r3;
            }
            #pragma unroll
            for (int nd = 0; nd < 8; nd++) mma16816(O[nd], pf[kk], vf[nd]);
        }
    }

    // ---- epilogue: normalize, round to fp16, store ----
    const float i0 = 1.f / l0, i1 = 1.f / l1;
    const size_t base0 = (size_t)(b * Tseq + rowg0) * Cdim + h * HD;
    const size_t base1 = (size_t)(b * Tseq + rowg1) * Cdim + h * HD;
    #pragma unroll
    for (int nt = 0; nt < 8; nt++) {
        const int col = nt * 8 + t * 2;
        *(uint32_t*)(yf + base0 + col) = packhf(O[nt][0] * i0, O[nt][1] * i0);
        *(uint32_t*)(yf + base1 + col) = packhf(O[nt][2] * i1, O[nt][3] * i1);
    }
}

// ---------------- launch ----------------
extern "C" void kernel_launch(void* const* d_in, const int* in_sizes, int n_in,
                              void* d_out, int out_size)
{
    const float* x     = (const float*)d_in[0];
    const float* qkv_w = (const float*)d_in[1];
    const float* qkv_b = (const float*)d_in[2];
    const float* out_w = (const float*)d_in[3];
    const float* out_b = (const float*)d_in[4];
    float* out = (float*)d_out;

    __half *xf, *qkvf, *yf, *wqf, *wof;
    cudaGetSymbolAddress((void**)&xf,   g_xf);
    cudaGetSymbolAddress((void**)&qkvf, g_qkvf);
    cudaGetSymbolAddress((void**)&yf,   g_yf);
    cudaGetSymbolAddress((void**)&wqf,  g_wqf);
    cudaGetSymbolAddress((void**)&wof,  g_wof);

    cudaFuncSetAttribute(gemm_mma<true>,  cudaFuncAttributeMaxDynamicSharedMemorySize, GEMM_SMEM);
    cudaFuncSetAttribute(gemm_mma<false>, cudaFuncAttributeMaxDynamicSharedMemorySize, GEMM_SMEM);
    cudaFuncSetAttribute(attn_mma, cudaFuncAttributeMaxDynamicSharedMemorySize, ATT_SMEM);

    const int M = Mrows;   // 8192

    // 0) fused prep
    prep_kernel<<<XB + WQB + WOB, 256>>>(x, xf, qkv_w, wqf, out_w, wof);

    // 1) QKV projection -> fp16 qkv
    gemm_mma<true><<<dim3(C3 / GBN, M / GBM), 256, GEMM_SMEM>>>(
        xf, wqf, qkv_b, nullptr, qkvf, M, C3, Cdim);

    // 2) causal attention -> fp16 y
    attn_mma<<<dim3(Tseq / 128, Bsz * Hn), 256, ATT_SMEM>>>(qkvf, yf);

    // 3) output projection -> fp32 out
    gemm_mma<false><<<dim3(Cdim / GBN, M / GBM), 256, GEMM_SMEM>>>(
        yf, wof, out_b, out, nullptr, M, Cdim, Cdim);
}